// round 8
// baseline (speedup 1.0000x reference)
#include <cuda_runtime.h>
#include <math.h>

#define BB   4
#define SS   2048
#define HH   1024
#define NHH  16
#define HDD  64
#define MM   (BB*SS)   /* 8192 tokens */
#define PW   4096      /* packed proj width: q|k|v|g */

// ---------------- scratch (device globals: allocation-free) ----------------
__device__ float g_proj[(size_t)MM*PW];      // packed q|k|v|g (raw gemm out)
__device__ float g_ab[(size_t)MM*2*NHH];
__device__ float g_attn[(size_t)MM*HH];
__device__ float g_z[(size_t)MM*HH];
__device__ float g_xr[(size_t)MM*HH];        // tf32-rounded x
__device__ float g_wr[(size_t)5*HH*HH];      // tf32-rounded Wq,Wk,Wv,Wg,Wo

// ---------------------------------------------------------------------------
// packed f32x2 helpers
// ---------------------------------------------------------------------------
typedef unsigned long long ull;
__device__ __forceinline__ ull pk2(float x, float y) {
    ull r; asm("mov.b64 %0, {%1,%2};" : "=l"(r) : "f"(x), "f"(y)); return r;
}
__device__ __forceinline__ ull mul2(ull a, ull b) {
    ull d; asm("mul.rn.f32x2 %0, %1, %2;" : "=l"(d) : "l"(a), "l"(b)); return d;
}
__device__ __forceinline__ ull add2(ull a, ull b) {
    ull d; asm("add.rn.f32x2 %0, %1, %2;" : "=l"(d) : "l"(a), "l"(b)); return d;
}
__device__ __forceinline__ ull fma2(ull a, ull b, ull c) {
    ull d; asm("fma.rn.f32x2 %0, %1, %2, %3;" : "=l"(d) : "l"(a), "l"(b), "l"(c)); return d;
}
__device__ __forceinline__ float2 upk2(ull a) {
    float2 f; asm("mov.b64 {%0,%1}, %2;" : "=f"(f.x), "=f"(f.y) : "l"(a)); return f;
}

__device__ __forceinline__ void cp_async16(void* dst_smem, const void* src_gmem) {
    unsigned dst = (unsigned)__cvta_generic_to_shared(dst_smem);
    asm volatile("cp.async.cg.shared.global [%0], [%1], 16;\n" :: "r"(dst), "l"(src_gmem));
}
__device__ __forceinline__ void cp_async_commit() {
    asm volatile("cp.async.commit_group;\n");
}
__device__ __forceinline__ void cp_async_wait0() {
    asm volatile("cp.async.wait_group 0;\n");
}

__device__ __forceinline__ float to_tf32(float x) {
    unsigned u; asm("cvt.rna.tf32.f32 %0, %1;" : "=r"(u) : "f"(x));
    return __uint_as_float(u);
}

// ---------------------------------------------------------------------------
// tf32 tensor-core GEMM via mma.sync (unchanged from R7)
// ---------------------------------------------------------------------------
#define GS      3
#define CHK     32
#define NCHK    (HH/CHK)
#define LDA     36
#define TILE_FL (128*LDA)
#define STG_FL  (2*TILE_FL)
#define GSMEM_SZ (GS*STG_FL*4)

__device__ __forceinline__ void mma_tf32(float* c, const unsigned* a, const unsigned* b) {
    asm volatile(
        "mma.sync.aligned.m16n8k8.row.col.f32.tf32.tf32.f32 "
        "{%0,%1,%2,%3}, {%4,%5,%6,%7}, {%8,%9}, {%0,%1,%2,%3};"
        : "+f"(c[0]), "+f"(c[1]), "+f"(c[2]), "+f"(c[3])
        : "r"(a[0]), "r"(a[1]), "r"(a[2]), "r"(a[3]), "r"(b[0]), "r"(b[1]));
}

__device__ __forceinline__ void load_chunk_g(const float* __restrict__ A,
                                             const float* __restrict__ Bm,
                                             float* sm, int stage,
                                             int row0, int col0, int kbase, int tid)
{
    float* sa = sm + stage*STG_FL;
    float* sb = sa + TILE_FL;
    #pragma unroll
    for (int it = 0; it < 4; ++it) {
        const int n   = tid + it*256;
        const int row = n >> 3;
        const int fc  = (n & 7) << 2;
        cp_async16(sa + row*LDA + fc, A  + (size_t)(row0 + row)*HH + kbase + fc);
        cp_async16(sb + row*LDA + fc, Bm + (size_t)(col0 + row)*HH + kbase + fc);
    }
    cp_async_commit();
}

__global__ __launch_bounds__(256, 2) void gemm_tf32(const float* __restrict__ A,
                                                    const float* __restrict__ Bm,
                                                    float* __restrict__ C,
                                                    int ldc)
{
    extern __shared__ float sm[];
    const int tid  = threadIdx.x;
    const int wid  = tid >> 5;
    const int lane = tid & 31;
    const int wm   = wid & 1;
    const int wn   = wid >> 1;
    const int l4   = lane >> 2;
    const int lm   = lane & 3;
    const int row0 = blockIdx.y * 128;
    const int col0 = blockIdx.x * 128;

    float acc[4][4][4];
    #pragma unroll
    for (int mt = 0; mt < 4; ++mt)
        #pragma unroll
        for (int nt = 0; nt < 4; ++nt)
            #pragma unroll
            for (int r = 0; r < 4; ++r) acc[mt][nt][r] = 0.f;

    load_chunk_g(A, Bm, sm, 0, row0, col0, 0*CHK, tid);
    load_chunk_g(A, Bm, sm, 1, row0, col0, 1*CHK, tid);

    for (int c = 0; c < NCHK; ++c) {
        if (c + GS - 1 < NCHK)
            load_chunk_g(A, Bm, sm, (c + GS - 1) % GS, row0, col0, (c + GS - 1)*CHK, tid);

        if (c < NCHK - 2)       asm volatile("cp.async.wait_group 2;");
        else if (c == NCHK - 2) asm volatile("cp.async.wait_group 1;");
        else                    asm volatile("cp.async.wait_group 0;");
        __syncthreads();

        const float* sa = sm + (c % GS)*STG_FL;
        const float* sb = sa + TILE_FL;

        unsigned a[2][4][4], b[2][4][2];

        #pragma unroll
        for (int mt = 0; mt < 4; ++mt) {
            const float* ap = sa + (wm*64 + mt*16 + l4)*LDA + lm;
            a[0][mt][0] = __float_as_uint(ap[0]);
            a[0][mt][1] = __float_as_uint(ap[8*LDA]);
            a[0][mt][2] = __float_as_uint(ap[4]);
            a[0][mt][3] = __float_as_uint(ap[8*LDA + 4]);
        }
        #pragma unroll
        for (int nt = 0; nt < 4; ++nt) {
            const float* bp = sb + (wn*32 + nt*8 + l4)*LDA + lm;
            b[0][nt][0] = __float_as_uint(bp[0]);
            b[0][nt][1] = __float_as_uint(bp[4]);
        }

        #pragma unroll
        for (int ks = 0; ks < 4; ++ks) {
            const int cur = ks & 1, nxt = cur ^ 1;
            if (ks < 3) {
                const int kk = (ks + 1)*8;
                #pragma unroll
                for (int mt = 0; mt < 4; ++mt) {
                    const float* ap = sa + (wm*64 + mt*16 + l4)*LDA + kk + lm;
                    a[nxt][mt][0] = __float_as_uint(ap[0]);
                    a[nxt][mt][1] = __float_as_uint(ap[8*LDA]);
                    a[nxt][mt][2] = __float_as_uint(ap[4]);
                    a[nxt][mt][3] = __float_as_uint(ap[8*LDA + 4]);
                }
                #pragma unroll
                for (int nt = 0; nt < 4; ++nt) {
                    const float* bp = sb + (wn*32 + nt*8 + l4)*LDA + kk + lm;
                    b[nxt][nt][0] = __float_as_uint(bp[0]);
                    b[nxt][nt][1] = __float_as_uint(bp[4]);
                }
            }
            #pragma unroll
            for (int mt = 0; mt < 4; ++mt)
                #pragma unroll
                for (int nt = 0; nt < 4; ++nt)
                    mma_tf32(acc[mt][nt], a[cur][mt], b[cur][nt]);
        }
        __syncthreads();
    }

    #pragma unroll
    for (int mt = 0; mt < 4; ++mt) {
        const int rg = row0 + wm*64 + mt*16 + l4;
        #pragma unroll
        for (int nt = 0; nt < 4; ++nt) {
            const int cg = col0 + wn*32 + nt*8 + lm*2;
            float* p = C + (size_t)rg*ldc + cg;
            *(float2*)p            = make_float2(acc[mt][nt][0], acc[mt][nt][1]);
            *(float2*)(p + 8*ldc)  = make_float2(acc[mt][nt][2], acc[mt][nt][3]);
        }
    }
}

// ---------------------------------------------------------------------------
// fused tf32 pre-rounding: x + 5 weights
// ---------------------------------------------------------------------------
__global__ __launch_bounds__(256) void round_all(const float* __restrict__ x,
                                                 const float* __restrict__ Wq,
                                                 const float* __restrict__ Wk,
                                                 const float* __restrict__ Wv,
                                                 const float* __restrict__ Wg,
                                                 const float* __restrict__ Wo,
                                                 float* __restrict__ xr,
                                                 float* __restrict__ wr)
{
    const size_t XC = (size_t)MM*HH/4;
    const size_t WC = (size_t)HH*HH/4;
    const size_t idx = (size_t)blockIdx.x * 256 + threadIdx.x;

    const float4* src;
    float4* dst;
    size_t off;
    if (idx < XC) {
        src = (const float4*)x; dst = (float4*)xr; off = idx;
    } else {
        const size_t r = idx - XC;
        const int w = (int)(r / WC);
        off = r % WC;
        const float* ws = (w == 0) ? Wq : (w == 1) ? Wk : (w == 2) ? Wv : (w == 3) ? Wg : Wo;
        src = (const float4*)ws;
        dst = (float4*)(wr + (size_t)w*HH*HH);
    }
    float4 v = src[off];
    v.x = to_tf32(v.x); v.y = to_tf32(v.y);
    v.z = to_tf32(v.z); v.w = to_tf32(v.w);
    dst[off] = v;
}

// ---------------------------------------------------------------------------
// alpha/beta
// ---------------------------------------------------------------------------
__global__ __launch_bounds__(256) void ab_kernel(const float* __restrict__ x,
                                                 const float* __restrict__ Wa,
                                                 const float* __restrict__ ba,
                                                 const float* __restrict__ Wb,
                                                 const float* __restrict__ bb,
                                                 float* __restrict__ ab)
{
    const int m0  = blockIdx.x * 8;
    const int tid = threadIdx.x;
    __shared__ float xs[8][HH];

    for (int n = tid; n < 8 * HH / 4; n += 256) {
        const int tok = n / (HH/4);
        const int e4  = (n % (HH/4)) * 4;
        *(float4*)&xs[tok][e4] = *(const float4*)&x[(size_t)(m0 + tok)*HH + e4];
    }
    __syncthreads();

    const int warp = tid >> 5, lane = tid & 31;
    for (int o = warp; o < 32; o += 8) {
        const float* w = (o < 16) ? (Wa + (size_t)o*HH) : (Wb + (size_t)(o-16)*HH);
        float wr[32];
        #pragma unroll
        for (int u = 0; u < 32; ++u) wr[u] = w[lane + u*32];
        const float bias = (o < 16) ? ba[o] : bb[o-16];
        for (int tok = 0; tok < 8; ++tok) {
            float sum = 0.f;
            #pragma unroll
            for (int u = 0; u < 32; ++u)
                sum = fmaf(wr[u], xs[tok][lane + u*32], sum);
            #pragma unroll
            for (int off = 16; off; off >>= 1)
                sum += __shfl_xor_sync(0xffffffffu, sum, off);
            if (lane == 0) {
                float y = sum + bias;
                ab[(size_t)(m0 + tok)*32 + o] = 1.f / (1.f + expf(-y));
            }
        }
    }
}

// ---------------------------------------------------------------------------
// Sequential scan with FUSED activations. 2 blocks per (b,h), each owns 32
// state rows. Per 16-step tile: stage raw q/k/v -> in-smem l2norm(k,q),
// silu(v), and precompute w[tt][j] = beta*k_j. Hot loop per step per thread:
// 4x (r=a*s; tmp=fma(-ki,r,vi); s=fma(w,tmp,r); p=fma(s,q,p)) on f32x2.
// ---------------------------------------------------------------------------
#define TILE 16
#define NTILE (SS/TILE)
#define SC_K(bufi)   ((bufi)*TILE*64)
#define SC_V(bufi)   (2*TILE*64 + (bufi)*TILE*64)
#define SC_Q(bufi)   (4*TILE*64 + (bufi)*TILE*64)
#define SC_AB        (6*TILE*64)
#define SC_W         (6*TILE*64 + SS*2)
#define SC_PART      (6*TILE*64 + SS*2 + TILE*64)
#define SCAN_SMEM_FL (6*TILE*64 + SS*2 + TILE*64 + TILE*32*8)
#define SCAN_SMEM_SZ (SCAN_SMEM_FL*4)   /* 61440 bytes */

__global__ __launch_bounds__(256) void scan_kernel(const float* __restrict__ proj,
                                                   const float* __restrict__ ab,
                                                   float* __restrict__ attn)
{
    extern __shared__ float sh[];
    const int bh2  = blockIdx.x;          // 0..127
    const int b    = bh2 >> 5;
    const int h    = (bh2 >> 1) & 15;
    const int half = bh2 & 1;
    const int tid  = threadIdx.x;
    const int i    = half*32 + (tid >> 3);   // state row 0..63
    const int c    = tid & 7;                // col group (8 cols)

    const float* q = proj;
    const float* k = proj + HH;
    const float* v = proj + 2*HH;

    auto base  = [&](int t) { return ((size_t)(b*SS + t) * PW + (size_t)h*HDD); };
    auto abase = [&](int t) { return ((size_t)(b*SS + t) * HH + (size_t)h*HDD); };

    {
        const int tt = tid >> 4;
        const int e4 = (tid & 15) << 2;
        cp_async16(&sh[SC_K(0) + tt*64 + e4], k + base(tt) + e4);
        cp_async16(&sh[SC_V(0) + tt*64 + e4], v + base(tt) + e4);
        cp_async16(&sh[SC_Q(0) + tt*64 + e4], q + base(tt) + e4);
        cp_async_commit();
    }
    for (int t = tid; t < SS; t += 256) {
        const size_t o = (size_t)(b*SS + t) * 32;
        sh[SC_AB + t*2 + 0] = ab[o + h];
        sh[SC_AB + t*2 + 1] = ab[o + 16 + h];
    }
    cp_async_wait0();
    __syncthreads();

    ull s2[4];
    #pragma unroll
    for (int j = 0; j < 4; ++j) s2[j] = 0ull;

    int buf = 0;
    for (int tile = 0; tile < NTILE; ++tile) {
        const int t0 = tile * TILE;
        if (tile + 1 < NTILE) {
            const int nx = buf ^ 1;
            const int tt = tid >> 4;
            const int e4 = (tid & 15) << 2;
            const size_t nb = base(t0 + TILE + tt) + e4;
            cp_async16(&sh[SC_K(nx) + tt*64 + e4], k + nb);
            cp_async16(&sh[SC_V(nx) + tt*64 + e4], v + nb);
            cp_async16(&sh[SC_Q(nx) + tt*64 + e4], q + nb);
            cp_async_commit();
        }

        // ---- in-smem activation pass: l2norm(k,q), silu(v), w = beta*khat ----
        {
            const int tt2 = tid >> 4;       // row 0..15
            const int e   = (tid & 15) * 4; // 4 elems per thread
            const float be = sh[SC_AB + (t0 + tt2)*2 + 1];
            float* kr = &sh[SC_K(buf) + tt2*64];
            float* qr = &sh[SC_Q(buf) + tt2*64];
            float* vr = &sh[SC_V(buf) + tt2*64];

            float4 k4 = *(float4*)&kr[e];
            float4 q4 = *(float4*)&qr[e];
            float ssk = k4.x*k4.x + k4.y*k4.y + k4.z*k4.z + k4.w*k4.w;
            float ssq = q4.x*q4.x + q4.y*q4.y + q4.z*q4.z + q4.w*q4.w;
            #pragma unroll
            for (int off = 8; off; off >>= 1) {
                ssk += __shfl_xor_sync(0xffffffffu, ssk, off);
                ssq += __shfl_xor_sync(0xffffffffu, ssq, off);
            }
            const float invk = 1.f / fmaxf(sqrtf(ssk), 1e-12f);
            const float invq = 1.f / fmaxf(sqrtf(ssq), 1e-12f);
            k4.x *= invk; k4.y *= invk; k4.z *= invk; k4.w *= invk;
            q4.x *= invq; q4.y *= invq; q4.z *= invq; q4.w *= invq;
            *(float4*)&kr[e] = k4;
            *(float4*)&qr[e] = q4;
            *(float4*)&sh[SC_W + tt2*64 + e] =
                make_float4(be*k4.x, be*k4.y, be*k4.z, be*k4.w);

            float4 v4 = *(float4*)&vr[e];
            v4.x = v4.x / (1.f + expf(-v4.x));
            v4.y = v4.y / (1.f + expf(-v4.y));
            v4.z = v4.z / (1.f + expf(-v4.z));
            v4.w = v4.w / (1.f + expf(-v4.w));
            *(float4*)&vr[e] = v4;
        }
        __syncthreads();

        const float* skb = &sh[SC_K(buf)];
        const float* svb = &sh[SC_V(buf)];
        const float* sqb = &sh[SC_Q(buf)];

        #pragma unroll 4
        for (int tt = 0; tt < TILE; ++tt) {
            const int t = t0 + tt;
            const float a  = sh[SC_AB + t*2];
            const float ki = skb[tt*64 + i];
            const float vi = svb[tt*64 + i];

            const ull a2   = pk2(a, a);
            const ull vi2  = pk2(vi, vi);
            const ull nki2 = pk2(-ki, -ki);

            ull w2[4], q2[4];
            {
                const ulonglong2* wp = (const ulonglong2*)&sh[SC_W + tt*64 + c*8];
                const ulonglong2* qp = (const ulonglong2*)&sqb[tt*64 + c*8];
                ulonglong2 ww0 = wp[0], ww1 = wp[1];
                ulonglong2 qq0 = qp[0], qq1 = qp[1];
                w2[0] = ww0.x; w2[1] = ww0.y; w2[2] = ww1.x; w2[3] = ww1.y;
                q2[0] = qq0.x; q2[1] = qq0.y; q2[2] = qq1.x; q2[3] = qq1.y;
            }

            ull pa = 0ull, pb = 0ull;
            #pragma unroll
            for (int j = 0; j < 4; ++j) {
                const ull r   = mul2(a2, s2[j]);
                const ull tmp = fma2(nki2, r, vi2);
                s2[j] = fma2(w2[j], tmp, r);
                if (j & 1) pb = fma2(s2[j], q2[j], pb);
                else       pa = fma2(s2[j], q2[j], pa);
            }
            const float2 ps = upk2(add2(pa, pb));
            sh[SC_PART + tt*256 + tid] = ps.x + ps.y;
        }
        __syncthreads();

        {
            const int tt = tid >> 4;
            const int r2 = (tid & 15) << 1;
            const float* p0 = &sh[SC_PART + tt*256 + r2*8];
            float4 u0 = *(const float4*)(p0);
            float4 u1 = *(const float4*)(p0 + 4);
            float4 u2 = *(const float4*)(p0 + 8);
            float4 u3 = *(const float4*)(p0 + 12);
            float o0 = (u0.x+u0.y)+(u0.z+u0.w) + (u1.x+u1.y)+(u1.z+u1.w);
            float o1 = (u2.x+u2.y)+(u2.z+u2.w) + (u3.x+u3.y)+(u3.z+u3.w);
            *(float2*)&attn[abase(t0 + tt) + half*32 + r2] = make_float2(o0, o1);
        }

        if (tile + 1 < NTILE) cp_async_wait0();
        __syncthreads();
        buf ^= 1;
    }
}

// ---------------------------------------------------------------------------
// layernorm over H + gate (gate read raw from packed proj; silu applied here)
// ---------------------------------------------------------------------------
__global__ __launch_bounds__(256) void ln_gate_kernel(const float* __restrict__ attn,
                                                      const float* __restrict__ proj,
                                                      const float* __restrict__ ln_g,
                                                      const float* __restrict__ ln_b,
                                                      float* __restrict__ z)
{
    const int m   = blockIdx.x;
    const int tid = threadIdx.x;
    const size_t rb = (size_t)m * HH + tid*4;

    float4 xv = *(const float4*)&attn[rb];
    float s  = xv.x + xv.y + xv.z + xv.w;
    float ss = xv.x*xv.x + xv.y*xv.y + xv.z*xv.z + xv.w*xv.w;
    #pragma unroll
    for (int off = 16; off; off >>= 1) {
        s  += __shfl_xor_sync(0xffffffffu, s,  off);
        ss += __shfl_xor_sync(0xffffffffu, ss, off);
    }
    __shared__ float rs[8], rss[8];
    if ((tid & 31) == 0) { rs[tid>>5] = s; rss[tid>>5] = ss; }
    __syncthreads();
    float tot = 0.f, tots = 0.f;
    #pragma unroll
    for (int w = 0; w < 8; ++w) { tot += rs[w]; tots += rss[w]; }

    const float mean = tot * (1.f/HH);
    const float var  = tots * (1.f/HH) - mean*mean;
    const float inv  = rsqrtf(var + 1e-5f);

    float4 gv = *(const float4*)&proj[(size_t)m*PW + 3*HH + tid*4];
    float4 lg = *(const float4*)&ln_g[tid*4];
    float4 lb = *(const float4*)&ln_b[tid*4];

    float4 o;
    o.x = to_tf32(((xv.x-mean)*inv*lg.x + lb.x) * (gv.x / (1.f + expf(-gv.x))));
    o.y = to_tf32(((xv.y-mean)*inv*lg.y + lb.y) * (gv.y / (1.f + expf(-gv.y))));
    o.z = to_tf32(((xv.z-mean)*inv*lg.z + lb.z) * (gv.z / (1.f + expf(-gv.z))));
    o.w = to_tf32(((xv.w-mean)*inv*lg.w + lb.w) * (gv.w / (1.f + expf(-gv.w))));
    *(float4*)&z[rb] = o;
}

// ---------------------------------------------------------------------------
extern "C" void kernel_launch(void* const* d_in, const int* in_sizes, int n_in,
                              void* d_out, int out_size)
{
    const float* x    = (const float*)d_in[0];
    const float* Wq   = (const float*)d_in[1];
    const float* Wk   = (const float*)d_in[2];
    const float* Wv   = (const float*)d_in[3];
    const float* Wa   = (const float*)d_in[4];
    const float* ba   = (const float*)d_in[5];
    const float* Wb   = (const float*)d_in[6];
    const float* bb   = (const float*)d_in[7];
    const float* Wg   = (const float*)d_in[8];
    const float* Wo   = (const float*)d_in[9];
    const float* ln_g = (const float*)d_in[10];
    const float* ln_b = (const float*)d_in[11];
    float* out = (float*)d_out;

    float *projp, *abp, *attnp, *zp, *xrp, *wrp;
    cudaGetSymbolAddress((void**)&projp, g_proj);
    cudaGetSymbolAddress((void**)&abp,   g_ab);
    cudaGetSymbolAddress((void**)&attnp, g_attn);
    cudaGetSymbolAddress((void**)&zp,    g_z);
    cudaGetSymbolAddress((void**)&xrp,   g_xr);
    cudaGetSymbolAddress((void**)&wrp,   g_wr);

    float* wo_r = wrp + 4*(size_t)HH*HH;

    cudaFuncSetAttribute(gemm_tf32, cudaFuncAttributeMaxDynamicSharedMemorySize, GSMEM_SZ);
    cudaFuncSetAttribute(scan_kernel, cudaFuncAttributeMaxDynamicSharedMemorySize, SCAN_SMEM_SZ);

    const int round_blocks = (MM*HH + 5*HH*HH) / (4*256);

    // 0: fused tf32 rounding
    round_all<<<round_blocks, 256>>>(x, Wq, Wk, Wv, Wg, Wo, xrp, wrp);
    // 1: alpha/beta
    ab_kernel<<<MM/8, 256>>>(x, Wa, ba, Wb, bb, abp);
    // 2: fused QKVG projection
    dim3 grid_qkvg(PW/128, MM/128);
    gemm_tf32<<<grid_qkvg, 256, GSMEM_SZ>>>(xrp, wrp, projp, PW);
    // 3: scan w/ fused activations  (ncu capture slot = our 3rd launch)
    scan_kernel<<<2*BB*NHH, 256, SCAN_SMEM_SZ>>>(projp, abp, attnp);
    // 4: LN + gate
    ln_gate_kernel<<<MM, 256>>>(attnp, projp, ln_g, ln_b, zp);
    // 5: output projection
    dim3 grid_o(HH/128, MM/128);
    gemm_tf32<<<grid_o, 256, GSMEM_SZ>>>(zp, wo_r, out, HH);
}

// round 9
// speedup vs baseline: 1.1764x; 1.1764x over previous
#include <cuda_runtime.h>
#include <math.h>

#define BB   4
#define SS   2048
#define HH   1024
#define NHH  16
#define HDD  64
#define MM   (BB*SS)   /* 8192 tokens */
#define PW   4096      /* packed proj width: q|k|v|g */

// ---------------- scratch (device globals: allocation-free) ----------------
__device__ float g_proj[(size_t)MM*PW];
__device__ float g_ab[(size_t)MM*2*NHH];
__device__ float g_attn[(size_t)MM*HH];
__device__ float g_z[(size_t)MM*HH];
__device__ float g_xr[(size_t)MM*HH];
__device__ float g_wr[(size_t)5*HH*HH];

// ---------------------------------------------------------------------------
// packed f32x2 helpers
// ---------------------------------------------------------------------------
typedef unsigned long long ull;
__device__ __forceinline__ ull pk2(float x, float y) {
    ull r; asm("mov.b64 %0, {%1,%2};" : "=l"(r) : "f"(x), "f"(y)); return r;
}
__device__ __forceinline__ ull mul2(ull a, ull b) {
    ull d; asm("mul.rn.f32x2 %0, %1, %2;" : "=l"(d) : "l"(a), "l"(b)); return d;
}
__device__ __forceinline__ ull add2(ull a, ull b) {
    ull d; asm("add.rn.f32x2 %0, %1, %2;" : "=l"(d) : "l"(a), "l"(b)); return d;
}
__device__ __forceinline__ ull fma2(ull a, ull b, ull c) {
    ull d; asm("fma.rn.f32x2 %0, %1, %2, %3;" : "=l"(d) : "l"(a), "l"(b), "l"(c)); return d;
}
__device__ __forceinline__ float2 upk2(ull a) {
    float2 f; asm("mov.b64 {%0,%1}, %2;" : "=f"(f.x), "=f"(f.y) : "l"(a)); return f;
}

__device__ __forceinline__ void cp_async16(void* dst_smem, const void* src_gmem) {
    unsigned dst = (unsigned)__cvta_generic_to_shared(dst_smem);
    asm volatile("cp.async.cg.shared.global [%0], [%1], 16;\n" :: "r"(dst), "l"(src_gmem));
}
__device__ __forceinline__ void cp_async_commit() {
    asm volatile("cp.async.commit_group;\n");
}
__device__ __forceinline__ void cp_async_wait0() {
    asm volatile("cp.async.wait_group 0;\n");
}

__device__ __forceinline__ float to_tf32(float x) {
    unsigned u; asm("cvt.rna.tf32.f32 %0, %1;" : "=r"(u) : "f"(x));
    return __uint_as_float(u);
}

#define LDSM_X4(r0, r1, r2, r3, addr) \
    asm volatile("ldmatrix.sync.aligned.m8n8.x4.shared.b16 {%0,%1,%2,%3}, [%4];" \
        : "=r"(r0), "=r"(r1), "=r"(r2), "=r"(r3) : "r"(addr))

// ---------------------------------------------------------------------------
// tf32 tensor-core GEMM: C[M,N] = A[M,K=1024] @ B[N,K]^T.
// Block tile 128x128, K-chunks of 32, 3-stage cp.async ring, 8 warps (2m x 4n),
// warp tile 64x32. Fragment loads via ldmatrix.x4 (6 LDSM/ks vs 96 LDS.32).
// ---------------------------------------------------------------------------
#define GS      3
#define CHK     32
#define NCHK    (HH/CHK)
#define LDA     36
#define TILE_FL (128*LDA)
#define STG_FL  (2*TILE_FL)
#define GSMEM_SZ (GS*STG_FL*4)

__device__ __forceinline__ void mma_tf32(float* c, const unsigned* a, const unsigned* b) {
    asm volatile(
        "mma.sync.aligned.m16n8k8.row.col.f32.tf32.tf32.f32 "
        "{%0,%1,%2,%3}, {%4,%5,%6,%7}, {%8,%9}, {%0,%1,%2,%3};"
        : "+f"(c[0]), "+f"(c[1]), "+f"(c[2]), "+f"(c[3])
        : "r"(a[0]), "r"(a[1]), "r"(a[2]), "r"(a[3]), "r"(b[0]), "r"(b[1]));
}

__device__ __forceinline__ void load_chunk_g(const float* __restrict__ A,
                                             const float* __restrict__ Bm,
                                             float* sm, int stage,
                                             int row0, int col0, int kbase, int tid)
{
    float* sa = sm + stage*STG_FL;
    float* sb = sa + TILE_FL;
    #pragma unroll
    for (int it = 0; it < 4; ++it) {
        const int n   = tid + it*256;
        const int row = n >> 3;
        const int fc  = (n & 7) << 2;
        cp_async16(sa + row*LDA + fc, A  + (size_t)(row0 + row)*HH + kbase + fc);
        cp_async16(sb + row*LDA + fc, Bm + (size_t)(col0 + row)*HH + kbase + fc);
    }
    cp_async_commit();
}

__global__ __launch_bounds__(256, 2) void gemm_tf32(const float* __restrict__ A,
                                                    const float* __restrict__ Bm,
                                                    float* __restrict__ C,
                                                    int ldc)
{
    extern __shared__ float sm[];
    const unsigned smu = (unsigned)__cvta_generic_to_shared(sm);
    const int tid  = threadIdx.x;
    const int wid  = tid >> 5;
    const int lane = tid & 31;
    const int wm   = wid & 1;
    const int wn   = wid >> 1;
    const int l4   = lane >> 2;
    const int lm   = lane & 3;
    const int row0 = blockIdx.y * 128;
    const int col0 = blockIdx.x * 128;

    // ldmatrix per-lane byte offsets (within a stage's A / B tile)
    const int tile = lane >> 3;      // which 8x8 tile this lane addresses
    const int trow = lane & 7;
    int a_byte[4], b_byte[2];
    #pragma unroll
    for (int mt = 0; mt < 4; ++mt)
        a_byte[mt] = ((wm*64 + mt*16 + ((tile & 1) << 3) + trow)*LDA
                      + ((tile >> 1) << 2)) * 4;
    #pragma unroll
    for (int p = 0; p < 2; ++p)
        b_byte[p] = ((wn*32 + (p*2 + (tile >> 1))*8 + trow)*LDA
                     + ((tile & 1) << 2)) * 4;

    float acc[4][4][4];
    #pragma unroll
    for (int mt = 0; mt < 4; ++mt)
        #pragma unroll
        for (int nt = 0; nt < 4; ++nt)
            #pragma unroll
            for (int r = 0; r < 4; ++r) acc[mt][nt][r] = 0.f;

    load_chunk_g(A, Bm, sm, 0, row0, col0, 0*CHK, tid);
    load_chunk_g(A, Bm, sm, 1, row0, col0, 1*CHK, tid);

    for (int c = 0; c < NCHK; ++c) {
        if (c + GS - 1 < NCHK)
            load_chunk_g(A, Bm, sm, (c + GS - 1) % GS, row0, col0, (c + GS - 1)*CHK, tid);

        if (c < NCHK - 2)       asm volatile("cp.async.wait_group 2;");
        else if (c == NCHK - 2) asm volatile("cp.async.wait_group 1;");
        else                    asm volatile("cp.async.wait_group 0;");
        __syncthreads();

        const unsigned sa_u = smu + ((unsigned)((c % GS)*STG_FL))*4u;
        const unsigned sb_u = sa_u + TILE_FL*4u;

        #pragma unroll
        for (int ks = 0; ks < 4; ++ks) {
            unsigned Af[4][4], Bf[2][4];
            #pragma unroll
            for (int mt = 0; mt < 4; ++mt)
                LDSM_X4(Af[mt][0], Af[mt][1], Af[mt][2], Af[mt][3],
                        sa_u + a_byte[mt] + ks*32);
            #pragma unroll
            for (int p = 0; p < 2; ++p)
                LDSM_X4(Bf[p][0], Bf[p][1], Bf[p][2], Bf[p][3],
                        sb_u + b_byte[p] + ks*32);
            #pragma unroll
            for (int mt = 0; mt < 4; ++mt)
                #pragma unroll
                for (int nt = 0; nt < 4; ++nt)
                    mma_tf32(acc[mt][nt], Af[mt], &Bf[nt >> 1][(nt & 1)*2]);
        }
        __syncthreads();
    }

    #pragma unroll
    for (int mt = 0; mt < 4; ++mt) {
        const int rg = row0 + wm*64 + mt*16 + l4;
        #pragma unroll
        for (int nt = 0; nt < 4; ++nt) {
            const int cg = col0 + wn*32 + nt*8 + lm*2;
            float* p = C + (size_t)rg*ldc + cg;
            *(float2*)p            = make_float2(acc[mt][nt][0], acc[mt][nt][1]);
            *(float2*)(p + 8*ldc)  = make_float2(acc[mt][nt][2], acc[mt][nt][3]);
        }
    }
}

// ---------------------------------------------------------------------------
// fused tf32 pre-rounding: x + 5 weights
// ---------------------------------------------------------------------------
__global__ __launch_bounds__(256) void round_all(const float* __restrict__ x,
                                                 const float* __restrict__ Wq,
                                                 const float* __restrict__ Wk,
                                                 const float* __restrict__ Wv,
                                                 const float* __restrict__ Wg,
                                                 const float* __restrict__ Wo,
                                                 float* __restrict__ xr,
                                                 float* __restrict__ wr)
{
    const size_t XC = (size_t)MM*HH/4;
    const size_t WC = (size_t)HH*HH/4;
    const size_t idx = (size_t)blockIdx.x * 256 + threadIdx.x;

    const float4* src;
    float4* dst;
    size_t off;
    if (idx < XC) {
        src = (const float4*)x; dst = (float4*)xr; off = idx;
    } else {
        const size_t r = idx - XC;
        const int w = (int)(r / WC);
        off = r % WC;
        const float* ws = (w == 0) ? Wq : (w == 1) ? Wk : (w == 2) ? Wv : (w == 3) ? Wg : Wo;
        src = (const float4*)ws;
        dst = (float4*)(wr + (size_t)w*HH*HH);
    }
    float4 v = src[off];
    v.x = to_tf32(v.x); v.y = to_tf32(v.y);
    v.z = to_tf32(v.z); v.w = to_tf32(v.w);
    dst[off] = v;
}

// ---------------------------------------------------------------------------
// alpha/beta
// ---------------------------------------------------------------------------
__global__ __launch_bounds__(256) void ab_kernel(const float* __restrict__ x,
                                                 const float* __restrict__ Wa,
                                                 const float* __restrict__ ba,
                                                 const float* __restrict__ Wb,
                                                 const float* __restrict__ bb,
                                                 float* __restrict__ ab)
{
    const int m0  = blockIdx.x * 8;
    const int tid = threadIdx.x;
    __shared__ float xs[8][HH];

    for (int n = tid; n < 8 * HH / 4; n += 256) {
        const int tok = n / (HH/4);
        const int e4  = (n % (HH/4)) * 4;
        *(float4*)&xs[tok][e4] = *(const float4*)&x[(size_t)(m0 + tok)*HH + e4];
    }
    __syncthreads();

    const int warp = tid >> 5, lane = tid & 31;
    for (int o = warp; o < 32; o += 8) {
        const float* w = (o < 16) ? (Wa + (size_t)o*HH) : (Wb + (size_t)(o-16)*HH);
        float wr[32];
        #pragma unroll
        for (int u = 0; u < 32; ++u) wr[u] = w[lane + u*32];
        const float bias = (o < 16) ? ba[o] : bb[o-16];
        for (int tok = 0; tok < 8; ++tok) {
            float sum = 0.f;
            #pragma unroll
            for (int u = 0; u < 32; ++u)
                sum = fmaf(wr[u], xs[tok][lane + u*32], sum);
            #pragma unroll
            for (int off = 16; off; off >>= 1)
                sum += __shfl_xor_sync(0xffffffffu, sum, off);
            if (lane == 0) {
                float y = sum + bias;
                ab[(size_t)(m0 + tok)*32 + o] = 1.f / (1.f + expf(-y));
            }
        }
    }
}

// ---------------------------------------------------------------------------
// Sequential scan, fused activations, 2 rows/thread. 2 blocks per (b,h);
// 128 threads: row pair rp = tid>>3 (rows half*32+2rp, +1), col group c=tid&7.
// Halved LDS wavefronts vs 1-row/thread (w/q amortized over 2 rows).
// ---------------------------------------------------------------------------
#define TILE 16
#define NTILE (SS/TILE)
#define PART_STRIDE 260
#define SC_K(bufi)   ((bufi)*TILE*64)
#define SC_V(bufi)   (2*TILE*64 + (bufi)*TILE*64)
#define SC_Q(bufi)   (4*TILE*64 + (bufi)*TILE*64)
#define SC_AB        (6*TILE*64)
#define SC_W         (6*TILE*64 + SS*2)
#define SC_PART      (6*TILE*64 + SS*2 + TILE*64)
#define SCAN_SMEM_FL (SC_PART + TILE*PART_STRIDE)
#define SCAN_SMEM_SZ (SCAN_SMEM_FL*4)

__global__ __launch_bounds__(128) void scan_kernel(const float* __restrict__ proj,
                                                   const float* __restrict__ ab,
                                                   float* __restrict__ attn)
{
    extern __shared__ float sh[];
    const int bh2  = blockIdx.x;          // 0..127
    const int b    = bh2 >> 5;
    const int h    = (bh2 >> 1) & 15;
    const int half = bh2 & 1;
    const int tid  = threadIdx.x;         // 0..127
    const int rp   = tid >> 3;            // 0..15 (row pair)
    const int c    = tid & 7;             // col group (8 cols)
    const int i0   = half*32 + rp*2;      // first state row

    const float* q = proj;
    const float* k = proj + HH;
    const float* v = proj + 2*HH;

    auto base  = [&](int t) { return ((size_t)(b*SS + t) * PW + (size_t)h*HDD); };
    auto abase = [&](int t) { return ((size_t)(b*SS + t) * HH + (size_t)h*HDD); };

    // stage tile 0 (2 float4 per array per thread)
    {
        #pragma unroll
        for (int it = 0; it < 2; ++it) {
            const int n  = tid + it*128;      // 0..255
            const int tt = n >> 4;
            const int e4 = (n & 15) << 2;
            cp_async16(&sh[SC_K(0) + tt*64 + e4], k + base(tt) + e4);
            cp_async16(&sh[SC_V(0) + tt*64 + e4], v + base(tt) + e4);
            cp_async16(&sh[SC_Q(0) + tt*64 + e4], q + base(tt) + e4);
        }
        cp_async_commit();
    }
    for (int t = tid; t < SS; t += 128) {
        const size_t o = (size_t)(b*SS + t) * 32;
        sh[SC_AB + t*2 + 0] = ab[o + h];
        sh[SC_AB + t*2 + 1] = ab[o + 16 + h];
    }
    cp_async_wait0();
    __syncthreads();

    ull s0[4], s1[4];
    #pragma unroll
    for (int j = 0; j < 4; ++j) { s0[j] = 0ull; s1[j] = 0ull; }

    int buf = 0;
    for (int tile = 0; tile < NTILE; ++tile) {
        const int t0 = tile * TILE;
        if (tile + 1 < NTILE) {
            const int nx = buf ^ 1;
            #pragma unroll
            for (int it = 0; it < 2; ++it) {
                const int n  = tid + it*128;
                const int tt = n >> 4;
                const int e4 = (n & 15) << 2;
                const size_t nb = base(t0 + TILE + tt) + e4;
                cp_async16(&sh[SC_K(nx) + tt*64 + e4], k + nb);
                cp_async16(&sh[SC_V(nx) + tt*64 + e4], v + nb);
                cp_async16(&sh[SC_Q(nx) + tt*64 + e4], q + nb);
            }
            cp_async_commit();
        }

        // ---- activation pass: l2norm(k,q), silu(v), w = beta*khat ----
        {
            const int tt2 = tid >> 3;        // step 0..15
            const int e   = (tid & 7) * 8;   // 8 floats per thread
            const float be = sh[SC_AB + (t0 + tt2)*2 + 1];
            float* kr = &sh[SC_K(buf) + tt2*64];
            float* qr = &sh[SC_Q(buf) + tt2*64];
            float* vr = &sh[SC_V(buf) + tt2*64];

            float4 ka = *(float4*)&kr[e], kb = *(float4*)&kr[e+4];
            float4 qa = *(float4*)&qr[e], qb = *(float4*)&qr[e+4];
            float ssk = ka.x*ka.x + ka.y*ka.y + ka.z*ka.z + ka.w*ka.w
                      + kb.x*kb.x + kb.y*kb.y + kb.z*kb.z + kb.w*kb.w;
            float ssq = qa.x*qa.x + qa.y*qa.y + qa.z*qa.z + qa.w*qa.w
                      + qb.x*qb.x + qb.y*qb.y + qb.z*qb.z + qb.w*qb.w;
            #pragma unroll
            for (int off = 4; off; off >>= 1) {
                ssk += __shfl_xor_sync(0xffffffffu, ssk, off);
                ssq += __shfl_xor_sync(0xffffffffu, ssq, off);
            }
            const float invk = 1.f / fmaxf(sqrtf(ssk), 1e-12f);
            const float invq = 1.f / fmaxf(sqrtf(ssq), 1e-12f);
            ka.x*=invk; ka.y*=invk; ka.z*=invk; ka.w*=invk;
            kb.x*=invk; kb.y*=invk; kb.z*=invk; kb.w*=invk;
            qa.x*=invq; qa.y*=invq; qa.z*=invq; qa.w*=invq;
            qb.x*=invq; qb.y*=invq; qb.z*=invq; qb.w*=invq;
            *(float4*)&kr[e]   = ka;  *(float4*)&kr[e+4] = kb;
            *(float4*)&qr[e]   = qa;  *(float4*)&qr[e+4] = qb;
            *(float4*)&sh[SC_W + tt2*64 + e]   = make_float4(be*ka.x, be*ka.y, be*ka.z, be*ka.w);
            *(float4*)&sh[SC_W + tt2*64 + e+4] = make_float4(be*kb.x, be*kb.y, be*kb.z, be*kb.w);

            float4 va = *(float4*)&vr[e], vb = *(float4*)&vr[e+4];
            va.x = va.x/(1.f+expf(-va.x)); va.y = va.y/(1.f+expf(-va.y));
            va.z = va.z/(1.f+expf(-va.z)); va.w = va.w/(1.f+expf(-va.w));
            vb.x = vb.x/(1.f+expf(-vb.x)); vb.y = vb.y/(1.f+expf(-vb.y));
            vb.z = vb.z/(1.f+expf(-vb.z)); vb.w = vb.w/(1.f+expf(-vb.w));
            *(float4*)&vr[e]   = va;  *(float4*)&vr[e+4] = vb;
        }
        __syncthreads();

        const float* skb = &sh[SC_K(buf)];
        const float* svb = &sh[SC_V(buf)];
        const float* sqb = &sh[SC_Q(buf)];

        #pragma unroll 4
        for (int tt = 0; tt < TILE; ++tt) {
            const int t = t0 + tt;
            const float a    = sh[SC_AB + t*2];
            const float2 kif = *(const float2*)&skb[tt*64 + i0];
            const float2 vif = *(const float2*)&svb[tt*64 + i0];

            const ull a2  = pk2(a, a);
            const ull nk0 = pk2(-kif.x, -kif.x);
            const ull nk1 = pk2(-kif.y, -kif.y);
            const ull v0  = pk2(vif.x, vif.x);
            const ull v1  = pk2(vif.y, vif.y);

            ull w2[4], q2[4];
            {
                const ulonglong2* wp = (const ulonglong2*)&sh[SC_W + tt*64 + c*8];
                const ulonglong2* qp = (const ulonglong2*)&sqb[tt*64 + c*8];
                ulonglong2 ww0 = wp[0], ww1 = wp[1];
                ulonglong2 qq0 = qp[0], qq1 = qp[1];
                w2[0]=ww0.x; w2[1]=ww0.y; w2[2]=ww1.x; w2[3]=ww1.y;
                q2[0]=qq0.x; q2[1]=qq0.y; q2[2]=qq1.x; q2[3]=qq1.y;
            }

            ull p0a=0ull, p0b=0ull, p1a=0ull, p1b=0ull;
            #pragma unroll
            for (int j = 0; j < 4; ++j) {
                const ull r0 = mul2(a2, s0[j]);
                const ull t0v = fma2(nk0, r0, v0);
                s0[j] = fma2(w2[j], t0v, r0);
                const ull r1 = mul2(a2, s1[j]);
                const ull t1v = fma2(nk1, r1, v1);
                s1[j] = fma2(w2[j], t1v, r1);
                if (j & 1) { p0b = fma2(s0[j], q2[j], p0b); p1b = fma2(s1[j], q2[j], p1b); }
                else       { p0a = fma2(s0[j], q2[j], p0a); p1a = fma2(s1[j], q2[j], p1a); }
            }
            const float2 x0 = upk2(add2(p0a, p0b));
            const float2 x1 = upk2(add2(p1a, p1b));
            sh[SC_PART + tt*PART_STRIDE + (rp*2+0)*8 + c] = x0.x + x0.y;
            sh[SC_PART + tt*PART_STRIDE + (rp*2+1)*8 + c] = x1.x + x1.y;
        }
        __syncthreads();

        // tile reduction: thread -> (step tt = tid&15, rows rowg*4..+3)
        {
            const int tt   = tid & 15;
            const int rowg = tid >> 4;     // 0..7
            const float* p0 = &sh[SC_PART + tt*PART_STRIDE + rowg*32];
            float out[4];
            #pragma unroll
            for (int r = 0; r < 4; ++r) {
                float4 u0 = *(const float4*)(p0 + r*8);
                float4 u1 = *(const float4*)(p0 + r*8 + 4);
                out[r] = (u0.x+u0.y)+(u0.z+u0.w) + (u1.x+u1.y)+(u1.z+u1.w);
            }
            *(float4*)&attn[abase(t0 + tt) + half*32 + rowg*4] =
                make_float4(out[0], out[1], out[2], out[3]);
        }

        if (tile + 1 < NTILE) cp_async_wait0();
        __syncthreads();
        buf ^= 1;
    }
}

// ---------------------------------------------------------------------------
// layernorm over H + gate; z pre-rounded to tf32
// ---------------------------------------------------------------------------
__global__ __launch_bounds__(256) void ln_gate_kernel(const float* __restrict__ attn,
                                                      const float* __restrict__ proj,
                                                      const float* __restrict__ ln_g,
                                                      const float* __restrict__ ln_b,
                                                      float* __restrict__ z)
{
    const int m   = blockIdx.x;
    const int tid = threadIdx.x;
    const size_t rb = (size_t)m * HH + tid*4;

    float4 xv = *(const float4*)&attn[rb];
    float s  = xv.x + xv.y + xv.z + xv.w;
    float ss = xv.x*xv.x + xv.y*xv.y + xv.z*xv.z + xv.w*xv.w;
    #pragma unroll
    for (int off = 16; off; off >>= 1) {
        s  += __shfl_xor_sync(0xffffffffu, s,  off);
        ss += __shfl_xor_sync(0xffffffffu, ss, off);
    }
    __shared__ float rs[8], rss[8];
    if ((tid & 31) == 0) { rs[tid>>5] = s; rss[tid>>5] = ss; }
    __syncthreads();
    float tot = 0.f, tots = 0.f;
    #pragma unroll
    for (int w = 0; w < 8; ++w) { tot += rs[w]; tots += rss[w]; }

    const float mean = tot * (1.f/HH);
    const float var  = tots * (1.f/HH) - mean*mean;
    const float inv  = rsqrtf(var + 1e-5f);

    float4 gv = *(const float4*)&proj[(size_t)m*PW + 3*HH + tid*4];
    float4 lg = *(const float4*)&ln_g[tid*4];
    float4 lb = *(const float4*)&ln_b[tid*4];

    float4 o;
    o.x = to_tf32(((xv.x-mean)*inv*lg.x + lb.x) * (gv.x / (1.f + expf(-gv.x))));
    o.y = to_tf32(((xv.y-mean)*inv*lg.y + lb.y) * (gv.y / (1.f + expf(-gv.y))));
    o.z = to_tf32(((xv.z-mean)*inv*lg.z + lb.z) * (gv.z / (1.f + expf(-gv.z))));
    o.w = to_tf32(((xv.w-mean)*inv*lg.w + lb.w) * (gv.w / (1.f + expf(-gv.w))));
    *(float4*)&z[rb] = o;
}

// ---------------------------------------------------------------------------
extern "C" void kernel_launch(void* const* d_in, const int* in_sizes, int n_in,
                              void* d_out, int out_size)
{
    const float* x    = (const float*)d_in[0];
    const float* Wq   = (const float*)d_in[1];
    const float* Wk   = (const float*)d_in[2];
    const float* Wv   = (const float*)d_in[3];
    const float* Wa   = (const float*)d_in[4];
    const float* ba   = (const float*)d_in[5];
    const float* Wb   = (const float*)d_in[6];
    const float* bb   = (const float*)d_in[7];
    const float* Wg   = (const float*)d_in[8];
    const float* Wo   = (const float*)d_in[9];
    const float* ln_g = (const float*)d_in[10];
    const float* ln_b = (const float*)d_in[11];
    float* out = (float*)d_out;

    float *projp, *abp, *attnp, *zp, *xrp, *wrp;
    cudaGetSymbolAddress((void**)&projp, g_proj);
    cudaGetSymbolAddress((void**)&abp,   g_ab);
    cudaGetSymbolAddress((void**)&attnp, g_attn);
    cudaGetSymbolAddress((void**)&zp,    g_z);
    cudaGetSymbolAddress((void**)&xrp,   g_xr);
    cudaGetSymbolAddress((void**)&wrp,   g_wr);

    float* wo_r = wrp + 4*(size_t)HH*HH;

    cudaFuncSetAttribute(gemm_tf32, cudaFuncAttributeMaxDynamicSharedMemorySize, GSMEM_SZ);
    cudaFuncSetAttribute(scan_kernel, cudaFuncAttributeMaxDynamicSharedMemorySize, SCAN_SMEM_SZ);

    const int round_blocks = (MM*HH + 5*HH*HH) / (4*256);

    // 0: fused tf32 rounding
    round_all<<<round_blocks, 256>>>(x, Wq, Wk, Wv, Wg, Wo, xrp, wrp);
    // 1: alpha/beta
    ab_kernel<<<MM/8, 256>>>(x, Wa, ba, Wb, bb, abp);
    // 2: fused QKVG projection
    dim3 grid_qkvg(PW/128, MM/128);
    gemm_tf32<<<grid_qkvg, 256, GSMEM_SZ>>>(xrp, wrp, projp, PW);
    // 3: scan (capture slot)
    scan_kernel<<<2*BB*NHH, 128, SCAN_SMEM_SZ>>>(projp, abp, attnp);
    // 4: LN + gate
    ln_gate_kernel<<<MM, 256>>>(attnp, projp, ln_g, ln_b, zp);
    // 5: output projection
    dim3 grid_o(HH/128, MM/128);
    gemm_tf32<<<grid_o, 256, GSMEM_SZ>>>(zp, wo_r, out, HH);
}

// round 10
// speedup vs baseline: 1.2095x; 1.0282x over previous
#include <cuda_runtime.h>
#include <math.h>

#define BB   4
#define SS   2048
#define HH   1024
#define NHH  16
#define HDD  64
#define MM   (BB*SS)   /* 8192 tokens */
#define PW   4096      /* packed proj width: q|k|v|g */

// ---------------- scratch (device globals: allocation-free) ----------------
__device__ float g_proj[(size_t)MM*PW];
__device__ float g_ab[(size_t)MM*2*NHH];
__device__ float g_attn[(size_t)MM*HH];
__device__ float g_z[(size_t)MM*HH];
__device__ float g_xr[(size_t)MM*HH];
__device__ float g_wr[(size_t)5*HH*HH];

// ---------------------------------------------------------------------------
// packed f32x2 helpers
// ---------------------------------------------------------------------------
typedef unsigned long long ull;
__device__ __forceinline__ ull pk2(float x, float y) {
    ull r; asm("mov.b64 %0, {%1,%2};" : "=l"(r) : "f"(x), "f"(y)); return r;
}
__device__ __forceinline__ ull mul2(ull a, ull b) {
    ull d; asm("mul.rn.f32x2 %0, %1, %2;" : "=l"(d) : "l"(a), "l"(b)); return d;
}
__device__ __forceinline__ ull add2(ull a, ull b) {
    ull d; asm("add.rn.f32x2 %0, %1, %2;" : "=l"(d) : "l"(a), "l"(b)); return d;
}
__device__ __forceinline__ ull fma2(ull a, ull b, ull c) {
    ull d; asm("fma.rn.f32x2 %0, %1, %2, %3;" : "=l"(d) : "l"(a), "l"(b), "l"(c)); return d;
}
__device__ __forceinline__ float2 upk2(ull a) {
    float2 f; asm("mov.b64 {%0,%1}, %2;" : "=f"(f.x), "=f"(f.y) : "l"(a)); return f;
}

__device__ __forceinline__ void cp_async16(void* dst_smem, const void* src_gmem) {
    unsigned dst = (unsigned)__cvta_generic_to_shared(dst_smem);
    asm volatile("cp.async.cg.shared.global [%0], [%1], 16;\n" :: "r"(dst), "l"(src_gmem));
}
__device__ __forceinline__ void cp_async_commit() {
    asm volatile("cp.async.commit_group;\n");
}
__device__ __forceinline__ void cp_async_wait0() {
    asm volatile("cp.async.wait_group 0;\n");
}

__device__ __forceinline__ float to_tf32(float x) {
    unsigned u; asm("cvt.rna.tf32.f32 %0, %1;" : "=r"(u) : "f"(x));
    return __uint_as_float(u);
}

__device__ __forceinline__ float fsigmoid(float x) {
    return 1.f / (1.f + __expf(-x));
}
__device__ __forceinline__ float fsilu(float x) {
    return x / (1.f + __expf(-x));
}

#define LDSM_X4(r0, r1, r2, r3, addr) \
    asm volatile("ldmatrix.sync.aligned.m8n8.x4.shared.b16 {%0,%1,%2,%3}, [%4];" \
        : "=r"(r0), "=r"(r1), "=r"(r2), "=r"(r3) : "r"(addr))

// ---------------------------------------------------------------------------
// tf32 tensor-core GEMM (unchanged from R9): block 128x128, K-chunks 32,
// 3-stage cp.async ring, ldmatrix fragment loads.
// ---------------------------------------------------------------------------
#define GS      3
#define CHK     32
#define NCHK    (HH/CHK)
#define LDA     36
#define TILE_FL (128*LDA)
#define STG_FL  (2*TILE_FL)
#define GSMEM_SZ (GS*STG_FL*4)

__device__ __forceinline__ void mma_tf32(float* c, const unsigned* a, const unsigned* b) {
    asm volatile(
        "mma.sync.aligned.m16n8k8.row.col.f32.tf32.tf32.f32 "
        "{%0,%1,%2,%3}, {%4,%5,%6,%7}, {%8,%9}, {%0,%1,%2,%3};"
        : "+f"(c[0]), "+f"(c[1]), "+f"(c[2]), "+f"(c[3])
        : "r"(a[0]), "r"(a[1]), "r"(a[2]), "r"(a[3]), "r"(b[0]), "r"(b[1]));
}

__device__ __forceinline__ void load_chunk_g(const float* __restrict__ A,
                                             const float* __restrict__ Bm,
                                             float* sm, int stage,
                                             int row0, int col0, int kbase, int tid)
{
    float* sa = sm + stage*STG_FL;
    float* sb = sa + TILE_FL;
    #pragma unroll
    for (int it = 0; it < 4; ++it) {
        const int n   = tid + it*256;
        const int row = n >> 3;
        const int fc  = (n & 7) << 2;
        cp_async16(sa + row*LDA + fc, A  + (size_t)(row0 + row)*HH + kbase + fc);
        cp_async16(sb + row*LDA + fc, Bm + (size_t)(col0 + row)*HH + kbase + fc);
    }
    cp_async_commit();
}

__global__ __launch_bounds__(256, 2) void gemm_tf32(const float* __restrict__ A,
                                                    const float* __restrict__ Bm,
                                                    float* __restrict__ C,
                                                    int ldc)
{
    extern __shared__ float sm[];
    const unsigned smu = (unsigned)__cvta_generic_to_shared(sm);
    const int tid  = threadIdx.x;
    const int wid  = tid >> 5;
    const int lane = tid & 31;
    const int wm   = wid & 1;
    const int wn   = wid >> 1;
    const int l4   = lane >> 2;
    const int lm   = lane & 3;
    const int row0 = blockIdx.y * 128;
    const int col0 = blockIdx.x * 128;

    const int tile = lane >> 3;
    const int trow = lane & 7;
    int a_byte[4], b_byte[2];
    #pragma unroll
    for (int mt = 0; mt < 4; ++mt)
        a_byte[mt] = ((wm*64 + mt*16 + ((tile & 1) << 3) + trow)*LDA
                      + ((tile >> 1) << 2)) * 4;
    #pragma unroll
    for (int p = 0; p < 2; ++p)
        b_byte[p] = ((wn*32 + (p*2 + (tile >> 1))*8 + trow)*LDA
                     + ((tile & 1) << 2)) * 4;

    float acc[4][4][4];
    #pragma unroll
    for (int mt = 0; mt < 4; ++mt)
        #pragma unroll
        for (int nt = 0; nt < 4; ++nt)
            #pragma unroll
            for (int r = 0; r < 4; ++r) acc[mt][nt][r] = 0.f;

    load_chunk_g(A, Bm, sm, 0, row0, col0, 0*CHK, tid);
    load_chunk_g(A, Bm, sm, 1, row0, col0, 1*CHK, tid);

    for (int c = 0; c < NCHK; ++c) {
        if (c + GS - 1 < NCHK)
            load_chunk_g(A, Bm, sm, (c + GS - 1) % GS, row0, col0, (c + GS - 1)*CHK, tid);

        if (c < NCHK - 2)       asm volatile("cp.async.wait_group 2;");
        else if (c == NCHK - 2) asm volatile("cp.async.wait_group 1;");
        else                    asm volatile("cp.async.wait_group 0;");
        __syncthreads();

        const unsigned sa_u = smu + ((unsigned)((c % GS)*STG_FL))*4u;
        const unsigned sb_u = sa_u + TILE_FL*4u;

        #pragma unroll
        for (int ks = 0; ks < 4; ++ks) {
            unsigned Af[4][4], Bf[2][4];
            #pragma unroll
            for (int mt = 0; mt < 4; ++mt)
                LDSM_X4(Af[mt][0], Af[mt][1], Af[mt][2], Af[mt][3],
                        sa_u + a_byte[mt] + ks*32);
            #pragma unroll
            for (int p = 0; p < 2; ++p)
                LDSM_X4(Bf[p][0], Bf[p][1], Bf[p][2], Bf[p][3],
                        sb_u + b_byte[p] + ks*32);
            #pragma unroll
            for (int mt = 0; mt < 4; ++mt)
                #pragma unroll
                for (int nt = 0; nt < 4; ++nt)
                    mma_tf32(acc[mt][nt], Af[mt], &Bf[nt >> 1][(nt & 1)*2]);
        }
        __syncthreads();
    }

    #pragma unroll
    for (int mt = 0; mt < 4; ++mt) {
        const int rg = row0 + wm*64 + mt*16 + l4;
        #pragma unroll
        for (int nt = 0; nt < 4; ++nt) {
            const int cg = col0 + wn*32 + nt*8 + lm*2;
            float* p = C + (size_t)rg*ldc + cg;
            *(float2*)p            = make_float2(acc[mt][nt][0], acc[mt][nt][1]);
            *(float2*)(p + 8*ldc)  = make_float2(acc[mt][nt][2], acc[mt][nt][3]);
        }
    }
}

// ---------------------------------------------------------------------------
// fused tf32 pre-rounding: x + 5 weights
// ---------------------------------------------------------------------------
__global__ __launch_bounds__(256) void round_all(const float* __restrict__ x,
                                                 const float* __restrict__ Wq,
                                                 const float* __restrict__ Wk,
                                                 const float* __restrict__ Wv,
                                                 const float* __restrict__ Wg,
                                                 const float* __restrict__ Wo,
                                                 float* __restrict__ xr,
                                                 float* __restrict__ wr)
{
    const size_t XC = (size_t)MM*HH/4;
    const size_t WC = (size_t)HH*HH/4;
    const size_t idx = (size_t)blockIdx.x * 256 + threadIdx.x;

    const float4* src;
    float4* dst;
    size_t off;
    if (idx < XC) {
        src = (const float4*)x; dst = (float4*)xr; off = idx;
    } else {
        const size_t r = idx - XC;
        const int w = (int)(r / WC);
        off = r % WC;
        const float* ws = (w == 0) ? Wq : (w == 1) ? Wk : (w == 2) ? Wv : (w == 3) ? Wg : Wo;
        src = (const float4*)ws;
        dst = (float4*)(wr + (size_t)w*HH*HH);
    }
    float4 v = src[off];
    v.x = to_tf32(v.x); v.y = to_tf32(v.y);
    v.z = to_tf32(v.z); v.w = to_tf32(v.w);
    dst[off] = v;
}

// ---------------------------------------------------------------------------
// alpha/beta
// ---------------------------------------------------------------------------
__global__ __launch_bounds__(256) void ab_kernel(const float* __restrict__ x,
                                                 const float* __restrict__ Wa,
                                                 const float* __restrict__ ba,
                                                 const float* __restrict__ Wb,
                                                 const float* __restrict__ bb,
                                                 float* __restrict__ ab)
{
    const int m0  = blockIdx.x * 8;
    const int tid = threadIdx.x;
    __shared__ float xs[8][HH];

    for (int n = tid; n < 8 * HH / 4; n += 256) {
        const int tok = n / (HH/4);
        const int e4  = (n % (HH/4)) * 4;
        *(float4*)&xs[tok][e4] = *(const float4*)&x[(size_t)(m0 + tok)*HH + e4];
    }
    __syncthreads();

    const int warp = tid >> 5, lane = tid & 31;
    for (int o = warp; o < 32; o += 8) {
        const float* w = (o < 16) ? (Wa + (size_t)o*HH) : (Wb + (size_t)(o-16)*HH);
        float wr[32];
        #pragma unroll
        for (int u = 0; u < 32; ++u) wr[u] = w[lane + u*32];
        const float bias = (o < 16) ? ba[o] : bb[o-16];
        for (int tok = 0; tok < 8; ++tok) {
            float sum = 0.f;
            #pragma unroll
            for (int u = 0; u < 32; ++u)
                sum = fmaf(wr[u], xs[tok][lane + u*32], sum);
            #pragma unroll
            for (int off = 16; off; off >>= 1)
                sum += __shfl_xor_sync(0xffffffffu, sum, off);
            if (lane == 0)
                ab[(size_t)(m0 + tok)*32 + o] = fsigmoid(sum + bias);
        }
    }
}

// ---------------------------------------------------------------------------
// Sequential scan, fused activations, 2 rows/thread, SOFTWARE-PIPELINED:
// step tt+1's w/q/ki/vi/a are loaded into a register double-buffer while
// step tt's 32-op fma2 burst issues (1 warp/SMSP -> ILP is the only latency
// hiding available; LDS 29cyc is fully covered by ~64 issue cycles).
// ---------------------------------------------------------------------------
#define TILE 16
#define NTILE (SS/TILE)
#define PART_STRIDE 260
#define SC_K(bufi)   ((bufi)*TILE*64)
#define SC_V(bufi)   (2*TILE*64 + (bufi)*TILE*64)
#define SC_Q(bufi)   (4*TILE*64 + (bufi)*TILE*64)
#define SC_AB        (6*TILE*64)
#define SC_W         (6*TILE*64 + SS*2)
#define SC_PART      (6*TILE*64 + SS*2 + TILE*64)
#define SCAN_SMEM_FL (SC_PART + TILE*PART_STRIDE)
#define SCAN_SMEM_SZ (SCAN_SMEM_FL*4)

__global__ __launch_bounds__(128) void scan_kernel(const float* __restrict__ proj,
                                                   const float* __restrict__ ab,
                                                   float* __restrict__ attn)
{
    extern __shared__ float sh[];
    const int bh2  = blockIdx.x;          // 0..127
    const int b    = bh2 >> 5;
    const int h    = (bh2 >> 1) & 15;
    const int half = bh2 & 1;
    const int tid  = threadIdx.x;         // 0..127
    const int rp   = tid >> 3;            // 0..15 (row pair)
    const int c    = tid & 7;             // col group (8 cols)
    const int i0   = half*32 + rp*2;      // first state row

    const float* q = proj;
    const float* k = proj + HH;
    const float* v = proj + 2*HH;

    auto base  = [&](int t) { return ((size_t)(b*SS + t) * PW + (size_t)h*HDD); };
    auto abase = [&](int t) { return ((size_t)(b*SS + t) * HH + (size_t)h*HDD); };

    {
        #pragma unroll
        for (int it = 0; it < 2; ++it) {
            const int n  = tid + it*128;
            const int tt = n >> 4;
            const int e4 = (n & 15) << 2;
            cp_async16(&sh[SC_K(0) + tt*64 + e4], k + base(tt) + e4);
            cp_async16(&sh[SC_V(0) + tt*64 + e4], v + base(tt) + e4);
            cp_async16(&sh[SC_Q(0) + tt*64 + e4], q + base(tt) + e4);
        }
        cp_async_commit();
    }
    for (int t = tid; t < SS; t += 128) {
        const size_t o = (size_t)(b*SS + t) * 32;
        sh[SC_AB + t*2 + 0] = ab[o + h];
        sh[SC_AB + t*2 + 1] = ab[o + 16 + h];
    }
    cp_async_wait0();
    __syncthreads();

    ull s0[4], s1[4];
    #pragma unroll
    for (int j = 0; j < 4; ++j) { s0[j] = 0ull; s1[j] = 0ull; }

    int buf = 0;
    for (int tile = 0; tile < NTILE; ++tile) {
        const int t0 = tile * TILE;
        if (tile + 1 < NTILE) {
            const int nx = buf ^ 1;
            #pragma unroll
            for (int it = 0; it < 2; ++it) {
                const int n  = tid + it*128;
                const int tt = n >> 4;
                const int e4 = (n & 15) << 2;
                const size_t nb = base(t0 + TILE + tt) + e4;
                cp_async16(&sh[SC_K(nx) + tt*64 + e4], k + nb);
                cp_async16(&sh[SC_V(nx) + tt*64 + e4], v + nb);
                cp_async16(&sh[SC_Q(nx) + tt*64 + e4], q + nb);
            }
            cp_async_commit();
        }

        // ---- activation pass: l2norm(k,q), silu(v), w = beta*khat ----
        {
            const int tt2 = tid >> 3;
            const int e   = (tid & 7) * 8;
            const float be = sh[SC_AB + (t0 + tt2)*2 + 1];
            float* kr = &sh[SC_K(buf) + tt2*64];
            float* qr = &sh[SC_Q(buf) + tt2*64];
            float* vr = &sh[SC_V(buf) + tt2*64];

            float4 ka = *(float4*)&kr[e], kb = *(float4*)&kr[e+4];
            float4 qa = *(float4*)&qr[e], qb = *(float4*)&qr[e+4];
            float ssk = ka.x*ka.x + ka.y*ka.y + ka.z*ka.z + ka.w*ka.w
                      + kb.x*kb.x + kb.y*kb.y + kb.z*kb.z + kb.w*kb.w;
            float ssq = qa.x*qa.x + qa.y*qa.y + qa.z*qa.z + qa.w*qa.w
                      + qb.x*qb.x + qb.y*qb.y + qb.z*qb.z + qb.w*qb.w;
            #pragma unroll
            for (int off = 4; off; off >>= 1) {
                ssk += __shfl_xor_sync(0xffffffffu, ssk, off);
                ssq += __shfl_xor_sync(0xffffffffu, ssq, off);
            }
            const float invk = 1.f / fmaxf(sqrtf(ssk), 1e-12f);
            const float invq = 1.f / fmaxf(sqrtf(ssq), 1e-12f);
            ka.x*=invk; ka.y*=invk; ka.z*=invk; ka.w*=invk;
            kb.x*=invk; kb.y*=invk; kb.z*=invk; kb.w*=invk;
            qa.x*=invq; qa.y*=invq; qa.z*=invq; qa.w*=invq;
            qb.x*=invq; qb.y*=invq; qb.z*=invq; qb.w*=invq;
            *(float4*)&kr[e]   = ka;  *(float4*)&kr[e+4] = kb;
            *(float4*)&qr[e]   = qa;  *(float4*)&qr[e+4] = qb;
            *(float4*)&sh[SC_W + tt2*64 + e]   = make_float4(be*ka.x, be*ka.y, be*ka.z, be*ka.w);
            *(float4*)&sh[SC_W + tt2*64 + e+4] = make_float4(be*kb.x, be*kb.y, be*kb.z, be*kb.w);

            float4 va = *(float4*)&vr[e], vb = *(float4*)&vr[e+4];
            va.x = fsilu(va.x); va.y = fsilu(va.y); va.z = fsilu(va.z); va.w = fsilu(va.w);
            vb.x = fsilu(vb.x); vb.y = fsilu(vb.y); vb.z = fsilu(vb.z); vb.w = fsilu(vb.w);
            *(float4*)&vr[e]   = va;  *(float4*)&vr[e+4] = vb;
        }
        __syncthreads();

        const float* skb = &sh[SC_K(buf)];
        const float* svb = &sh[SC_V(buf)];
        const float* sqb = &sh[SC_Q(buf)];

        // register double-buffer for the per-step operands
        ull    w2[2][4], q2[2][4];
        float2 kif[2], vif[2];
        float  av[2];

        // preload step 0 into slot 0
        {
            const ulonglong2* wp = (const ulonglong2*)&sh[SC_W + c*8];
            const ulonglong2* qp = (const ulonglong2*)&sqb[c*8];
            ulonglong2 ww0 = wp[0], ww1 = wp[1];
            ulonglong2 qq0 = qp[0], qq1 = qp[1];
            w2[0][0]=ww0.x; w2[0][1]=ww0.y; w2[0][2]=ww1.x; w2[0][3]=ww1.y;
            q2[0][0]=qq0.x; q2[0][1]=qq0.y; q2[0][2]=qq1.x; q2[0][3]=qq1.y;
            kif[0] = *(const float2*)&skb[i0];
            vif[0] = *(const float2*)&svb[i0];
            av[0]  = sh[SC_AB + t0*2];
        }

        #pragma unroll
        for (int tt = 0; tt < TILE; ++tt) {
            const int cur = tt & 1;
            const int nxt = cur ^ 1;
            // issue next step's loads first (consumed ~64 issue-cycles later)
            if (tt + 1 < TILE) {
                const ulonglong2* wp = (const ulonglong2*)&sh[SC_W + (tt+1)*64 + c*8];
                const ulonglong2* qp = (const ulonglong2*)&sqb[(tt+1)*64 + c*8];
                ulonglong2 ww0 = wp[0], ww1 = wp[1];
                ulonglong2 qq0 = qp[0], qq1 = qp[1];
                w2[nxt][0]=ww0.x; w2[nxt][1]=ww0.y; w2[nxt][2]=ww1.x; w2[nxt][3]=ww1.y;
                q2[nxt][0]=qq0.x; q2[nxt][1]=qq0.y; q2[nxt][2]=qq1.x; q2[nxt][3]=qq1.y;
                kif[nxt] = *(const float2*)&skb[(tt+1)*64 + i0];
                vif[nxt] = *(const float2*)&svb[(tt+1)*64 + i0];
                av[nxt]  = sh[SC_AB + (t0+tt+1)*2];
            }

            const ull a2  = pk2(av[cur], av[cur]);
            const ull nk0 = pk2(-kif[cur].x, -kif[cur].x);
            const ull nk1 = pk2(-kif[cur].y, -kif[cur].y);
            const ull v0  = pk2(vif[cur].x, vif[cur].x);
            const ull v1  = pk2(vif[cur].y, vif[cur].y);

            ull p0a=0ull, p0b=0ull, p1a=0ull, p1b=0ull;
            #pragma unroll
            for (int j = 0; j < 4; ++j) {
                const ull r0  = mul2(a2, s0[j]);
                const ull t0v = fma2(nk0, r0, v0);
                s0[j] = fma2(w2[cur][j], t0v, r0);
                const ull r1  = mul2(a2, s1[j]);
                const ull t1v = fma2(nk1, r1, v1);
                s1[j] = fma2(w2[cur][j], t1v, r1);
                if (j & 1) { p0b = fma2(s0[j], q2[cur][j], p0b); p1b = fma2(s1[j], q2[cur][j], p1b); }
                else       { p0a = fma2(s0[j], q2[cur][j], p0a); p1a = fma2(s1[j], q2[cur][j], p1a); }
            }
            const float2 x0 = upk2(add2(p0a, p0b));
            const float2 x1 = upk2(add2(p1a, p1b));
            sh[SC_PART + tt*PART_STRIDE + (rp*2+0)*8 + c] = x0.x + x0.y;
            sh[SC_PART + tt*PART_STRIDE + (rp*2+1)*8 + c] = x1.x + x1.y;
        }
        __syncthreads();

        // tile reduction
        {
            const int tt   = tid & 15;
            const int rowg = tid >> 4;
            const float* p0 = &sh[SC_PART + tt*PART_STRIDE + rowg*32];
            float out[4];
            #pragma unroll
            for (int r = 0; r < 4; ++r) {
                float4 u0 = *(const float4*)(p0 + r*8);
                float4 u1 = *(const float4*)(p0 + r*8 + 4);
                out[r] = (u0.x+u0.y)+(u0.z+u0.w) + (u1.x+u1.y)+(u1.z+u1.w);
            }
            *(float4*)&attn[abase(t0 + tt) + half*32 + rowg*4] =
                make_float4(out[0], out[1], out[2], out[3]);
        }

        if (tile + 1 < NTILE) cp_async_wait0();
        __syncthreads();
        buf ^= 1;
    }
}

// ---------------------------------------------------------------------------
// layernorm over H + gate; z pre-rounded to tf32
// ---------------------------------------------------------------------------
__global__ __launch_bounds__(256) void ln_gate_kernel(const float* __restrict__ attn,
                                                      const float* __restrict__ proj,
                                                      const float* __restrict__ ln_g,
                                                      const float* __restrict__ ln_b,
                                                      float* __restrict__ z)
{
    const int m   = blockIdx.x;
    const int tid = threadIdx.x;
    const size_t rb = (size_t)m * HH + tid*4;

    float4 xv = *(const float4*)&attn[rb];
    float s  = xv.x + xv.y + xv.z + xv.w;
    float ss = xv.x*xv.x + xv.y*xv.y + xv.z*xv.z + xv.w*xv.w;
    #pragma unroll
    for (int off = 16; off; off >>= 1) {
        s  += __shfl_xor_sync(0xffffffffu, s,  off);
        ss += __shfl_xor_sync(0xffffffffu, ss, off);
    }
    __shared__ float rs[8], rss[8];
    if ((tid & 31) == 0) { rs[tid>>5] = s; rss[tid>>5] = ss; }
    __syncthreads();
    float tot = 0.f, tots = 0.f;
    #pragma unroll
    for (int w = 0; w < 8; ++w) { tot += rs[w]; tots += rss[w]; }

    const float mean = tot * (1.f/HH);
    const float var  = tots * (1.f/HH) - mean*mean;
    const float inv  = rsqrtf(var + 1e-5f);

    float4 gv = *(const float4*)&proj[(size_t)m*PW + 3*HH + tid*4];
    float4 lg = *(const float4*)&ln_g[tid*4];
    float4 lb = *(const float4*)&ln_b[tid*4];

    float4 o;
    o.x = to_tf32(((xv.x-mean)*inv*lg.x + lb.x) * fsilu(gv.x));
    o.y = to_tf32(((xv.y-mean)*inv*lg.y + lb.y) * fsilu(gv.y));
    o.z = to_tf32(((xv.z-mean)*inv*lg.z + lb.z) * fsilu(gv.z));
    o.w = to_tf32(((xv.w-mean)*inv*lg.w + lb.w) * fsilu(gv.w));
    *(float4*)&z[rb] = o;
}

// ---------------------------------------------------------------------------
extern "C" void kernel_launch(void* const* d_in, const int* in_sizes, int n_in,
                              void* d_out, int out_size)
{
    const float* x    = (const float*)d_in[0];
    const float* Wq   = (const float*)d_in[1];
    const float* Wk   = (const float*)d_in[2];
    const float* Wv   = (const float*)d_in[3];
    const float* Wa   = (const float*)d_in[4];
    const float* ba   = (const float*)d_in[5];
    const float* Wb   = (const float*)d_in[6];
    const float* bb   = (const float*)d_in[7];
    const float* Wg   = (const float*)d_in[8];
    const float* Wo   = (const float*)d_in[9];
    const float* ln_g = (const float*)d_in[10];
    const float* ln_b = (const float*)d_in[11];
    float* out = (float*)d_out;

    float *projp, *abp, *attnp, *zp, *xrp, *wrp;
    cudaGetSymbolAddress((void**)&projp, g_proj);
    cudaGetSymbolAddress((void**)&abp,   g_ab);
    cudaGetSymbolAddress((void**)&attnp, g_attn);
    cudaGetSymbolAddress((void**)&zp,    g_z);
    cudaGetSymbolAddress((void**)&xrp,   g_xr);
    cudaGetSymbolAddress((void**)&wrp,   g_wr);

    float* wo_r = wrp + 4*(size_t)HH*HH;

    cudaFuncSetAttribute(gemm_tf32, cudaFuncAttributeMaxDynamicSharedMemorySize, GSMEM_SZ);
    cudaFuncSetAttribute(scan_kernel, cudaFuncAttributeMaxDynamicSharedMemorySize, SCAN_SMEM_SZ);

    const int round_blocks = (MM*HH + 5*HH*HH) / (4*256);

    // 0: fused tf32 rounding
    round_all<<<round_blocks, 256>>>(x, Wq, Wk, Wv, Wg, Wo, xrp, wrp);
    // 1: alpha/beta
    ab_kernel<<<MM/8, 256>>>(x, Wa, ba, Wb, bb, abp);
    // 2: fused QKVG projection
    dim3 grid_qkvg(PW/128, MM/128);
    gemm_tf32<<<grid_qkvg, 256, GSMEM_SZ>>>(xrp, wrp, projp, PW);
    // 3: scan (capture slot)
    scan_kernel<<<2*BB*NHH, 128, SCAN_SMEM_SZ>>>(projp, abp, attnp);
    // 4: LN + gate
    ln_gate_kernel<<<MM, 256>>>(attnp, projp, ln_g, ln_b, zp);
    // 5: output projection
    dim3 grid_o(HH/128, MM/128);
    gemm_tf32<<<grid_o, 256, GSMEM_SZ>>>(zp, wo_r, out, HH);
}

// round 11
// speedup vs baseline: 1.2501x; 1.0336x over previous
#include <cuda_runtime.h>
#include <math.h>

#define BB   4
#define SS   2048
#define HH   1024
#define NHH  16
#define HDD  64
#define MM   (BB*SS)   /* 8192 tokens */
#define PW   4096      /* packed proj width: q|k|v|g */

// ---------------- scratch (device globals: allocation-free) ----------------
__device__ float g_proj[(size_t)MM*PW];
__device__ float g_ab[(size_t)MM*2*NHH];
__device__ float g_attn[(size_t)MM*HH];    // col-half 0 partial
__device__ float g_attn2[(size_t)MM*HH];   // col-half 1 partial
__device__ float g_z[(size_t)MM*HH];
__device__ float g_xr[(size_t)MM*HH];
__device__ float g_wr[(size_t)5*HH*HH];

// ---------------------------------------------------------------------------
// packed f32x2 helpers
// ---------------------------------------------------------------------------
typedef unsigned long long ull;
__device__ __forceinline__ ull pk2(float x, float y) {
    ull r; asm("mov.b64 %0, {%1,%2};" : "=l"(r) : "f"(x), "f"(y)); return r;
}
__device__ __forceinline__ ull mul2(ull a, ull b) {
    ull d; asm("mul.rn.f32x2 %0, %1, %2;" : "=l"(d) : "l"(a), "l"(b)); return d;
}
__device__ __forceinline__ ull add2(ull a, ull b) {
    ull d; asm("add.rn.f32x2 %0, %1, %2;" : "=l"(d) : "l"(a), "l"(b)); return d;
}
__device__ __forceinline__ ull fma2(ull a, ull b, ull c) {
    ull d; asm("fma.rn.f32x2 %0, %1, %2, %3;" : "=l"(d) : "l"(a), "l"(b), "l"(c)); return d;
}
__device__ __forceinline__ float2 upk2(ull a) {
    float2 f; asm("mov.b64 {%0,%1}, %2;" : "=f"(f.x), "=f"(f.y) : "l"(a)); return f;
}

__device__ __forceinline__ void cp_async16(void* dst_smem, const void* src_gmem) {
    unsigned dst = (unsigned)__cvta_generic_to_shared(dst_smem);
    asm volatile("cp.async.cg.shared.global [%0], [%1], 16;\n" :: "r"(dst), "l"(src_gmem));
}
__device__ __forceinline__ void cp_async_commit() {
    asm volatile("cp.async.commit_group;\n");
}
__device__ __forceinline__ void cp_async_wait0() {
    asm volatile("cp.async.wait_group 0;\n");
}

__device__ __forceinline__ float to_tf32(float x) {
    unsigned u; asm("cvt.rna.tf32.f32 %0, %1;" : "=r"(u) : "f"(x));
    return __uint_as_float(u);
}

__device__ __forceinline__ float fsigmoid(float x) {
    return 1.f / (1.f + __expf(-x));
}
__device__ __forceinline__ float fsilu(float x) {
    return x / (1.f + __expf(-x));
}

#define LDSM_X4(r0, r1, r2, r3, addr) \
    asm volatile("ldmatrix.sync.aligned.m8n8.x4.shared.b16 {%0,%1,%2,%3}, [%4];" \
        : "=r"(r0), "=r"(r1), "=r"(r2), "=r"(r3) : "r"(addr))

// ---------------------------------------------------------------------------
// tf32 tensor-core GEMM (unchanged from R9/R10)
// ---------------------------------------------------------------------------
#define GS      3
#define CHK     32
#define NCHK    (HH/CHK)
#define LDA     36
#define TILE_FL (128*LDA)
#define STG_FL  (2*TILE_FL)
#define GSMEM_SZ (GS*STG_FL*4)

__device__ __forceinline__ void mma_tf32(float* c, const unsigned* a, const unsigned* b) {
    asm volatile(
        "mma.sync.aligned.m16n8k8.row.col.f32.tf32.tf32.f32 "
        "{%0,%1,%2,%3}, {%4,%5,%6,%7}, {%8,%9}, {%0,%1,%2,%3};"
        : "+f"(c[0]), "+f"(c[1]), "+f"(c[2]), "+f"(c[3])
        : "r"(a[0]), "r"(a[1]), "r"(a[2]), "r"(a[3]), "r"(b[0]), "r"(b[1]));
}

__device__ __forceinline__ void load_chunk_g(const float* __restrict__ A,
                                             const float* __restrict__ Bm,
                                             float* sm, int stage,
                                             int row0, int col0, int kbase, int tid)
{
    float* sa = sm + stage*STG_FL;
    float* sb = sa + TILE_FL;
    #pragma unroll
    for (int it = 0; it < 4; ++it) {
        const int n   = tid + it*256;
        const int row = n >> 3;
        const int fc  = (n & 7) << 2;
        cp_async16(sa + row*LDA + fc, A  + (size_t)(row0 + row)*HH + kbase + fc);
        cp_async16(sb + row*LDA + fc, Bm + (size_t)(col0 + row)*HH + kbase + fc);
    }
    cp_async_commit();
}

__global__ __launch_bounds__(256, 2) void gemm_tf32(const float* __restrict__ A,
                                                    const float* __restrict__ Bm,
                                                    float* __restrict__ C,
                                                    int ldc)
{
    extern __shared__ float sm[];
    const unsigned smu = (unsigned)__cvta_generic_to_shared(sm);
    const int tid  = threadIdx.x;
    const int wid  = tid >> 5;
    const int lane = tid & 31;
    const int wm   = wid & 1;
    const int wn   = wid >> 1;
    const int l4   = lane >> 2;
    const int lm   = lane & 3;
    const int row0 = blockIdx.y * 128;
    const int col0 = blockIdx.x * 128;

    const int tile = lane >> 3;
    const int trow = lane & 7;
    int a_byte[4], b_byte[2];
    #pragma unroll
    for (int mt = 0; mt < 4; ++mt)
        a_byte[mt] = ((wm*64 + mt*16 + ((tile & 1) << 3) + trow)*LDA
                      + ((tile >> 1) << 2)) * 4;
    #pragma unroll
    for (int p = 0; p < 2; ++p)
        b_byte[p] = ((wn*32 + (p*2 + (tile >> 1))*8 + trow)*LDA
                     + ((tile & 1) << 2)) * 4;

    float acc[4][4][4];
    #pragma unroll
    for (int mt = 0; mt < 4; ++mt)
        #pragma unroll
        for (int nt = 0; nt < 4; ++nt)
            #pragma unroll
            for (int r = 0; r < 4; ++r) acc[mt][nt][r] = 0.f;

    load_chunk_g(A, Bm, sm, 0, row0, col0, 0*CHK, tid);
    load_chunk_g(A, Bm, sm, 1, row0, col0, 1*CHK, tid);

    for (int c = 0; c < NCHK; ++c) {
        if (c + GS - 1 < NCHK)
            load_chunk_g(A, Bm, sm, (c + GS - 1) % GS, row0, col0, (c + GS - 1)*CHK, tid);

        if (c < NCHK - 2)       asm volatile("cp.async.wait_group 2;");
        else if (c == NCHK - 2) asm volatile("cp.async.wait_group 1;");
        else                    asm volatile("cp.async.wait_group 0;");
        __syncthreads();

        const unsigned sa_u = smu + ((unsigned)((c % GS)*STG_FL))*4u;
        const unsigned sb_u = sa_u + TILE_FL*4u;

        #pragma unroll
        for (int ks = 0; ks < 4; ++ks) {
            unsigned Af[4][4], Bf[2][4];
            #pragma unroll
            for (int mt = 0; mt < 4; ++mt)
                LDSM_X4(Af[mt][0], Af[mt][1], Af[mt][2], Af[mt][3],
                        sa_u + a_byte[mt] + ks*32);
            #pragma unroll
            for (int p = 0; p < 2; ++p)
                LDSM_X4(Bf[p][0], Bf[p][1], Bf[p][2], Bf[p][3],
                        sb_u + b_byte[p] + ks*32);
            #pragma unroll
            for (int mt = 0; mt < 4; ++mt)
                #pragma unroll
                for (int nt = 0; nt < 4; ++nt)
                    mma_tf32(acc[mt][nt], Af[mt], &Bf[nt >> 1][(nt & 1)*2]);
        }
        __syncthreads();
    }

    #pragma unroll
    for (int mt = 0; mt < 4; ++mt) {
        const int rg = row0 + wm*64 + mt*16 + l4;
        #pragma unroll
        for (int nt = 0; nt < 4; ++nt) {
            const int cg = col0 + wn*32 + nt*8 + lm*2;
            float* p = C + (size_t)rg*ldc + cg;
            *(float2*)p            = make_float2(acc[mt][nt][0], acc[mt][nt][1]);
            *(float2*)(p + 8*ldc)  = make_float2(acc[mt][nt][2], acc[mt][nt][3]);
        }
    }
}

// ---------------------------------------------------------------------------
// fused tf32 pre-rounding: x + 5 weights
// ---------------------------------------------------------------------------
__global__ __launch_bounds__(256) void round_all(const float* __restrict__ x,
                                                 const float* __restrict__ Wq,
                                                 const float* __restrict__ Wk,
                                                 const float* __restrict__ Wv,
                                                 const float* __restrict__ Wg,
                                                 const float* __restrict__ Wo,
                                                 float* __restrict__ xr,
                                                 float* __restrict__ wr)
{
    const size_t XC = (size_t)MM*HH/4;
    const size_t WC = (size_t)HH*HH/4;
    const size_t idx = (size_t)blockIdx.x * 256 + threadIdx.x;

    const float4* src;
    float4* dst;
    size_t off;
    if (idx < XC) {
        src = (const float4*)x; dst = (float4*)xr; off = idx;
    } else {
        const size_t r = idx - XC;
        const int w = (int)(r / WC);
        off = r % WC;
        const float* ws = (w == 0) ? Wq : (w == 1) ? Wk : (w == 2) ? Wv : (w == 3) ? Wg : Wo;
        src = (const float4*)ws;
        dst = (float4*)(wr + (size_t)w*HH*HH);
    }
    float4 v = src[off];
    v.x = to_tf32(v.x); v.y = to_tf32(v.y);
    v.z = to_tf32(v.z); v.w = to_tf32(v.w);
    dst[off] = v;
}

// ---------------------------------------------------------------------------
// alpha/beta
// ---------------------------------------------------------------------------
__global__ __launch_bounds__(256) void ab_kernel(const float* __restrict__ x,
                                                 const float* __restrict__ Wa,
                                                 const float* __restrict__ ba,
                                                 const float* __restrict__ Wb,
                                                 const float* __restrict__ bb,
                                                 float* __restrict__ ab)
{
    const int m0  = blockIdx.x * 8;
    const int tid = threadIdx.x;
    __shared__ float xs[8][HH];

    for (int n = tid; n < 8 * HH / 4; n += 256) {
        const int tok = n / (HH/4);
        const int e4  = (n % (HH/4)) * 4;
        *(float4*)&xs[tok][e4] = *(const float4*)&x[(size_t)(m0 + tok)*HH + e4];
    }
    __syncthreads();

    const int warp = tid >> 5, lane = tid & 31;
    for (int o = warp; o < 32; o += 8) {
        const float* w = (o < 16) ? (Wa + (size_t)o*HH) : (Wb + (size_t)(o-16)*HH);
        float wr[32];
        #pragma unroll
        for (int u = 0; u < 32; ++u) wr[u] = w[lane + u*32];
        const float bias = (o < 16) ? ba[o] : bb[o-16];
        for (int tok = 0; tok < 8; ++tok) {
            float sum = 0.f;
            #pragma unroll
            for (int u = 0; u < 32; ++u)
                sum = fmaf(wr[u], xs[tok][lane + u*32], sum);
            #pragma unroll
            for (int off = 16; off; off >>= 1)
                sum += __shfl_xor_sync(0xffffffffu, sum, off);
            if (lane == 0)
                ab[(size_t)(m0 + tok)*32 + o] = fsigmoid(sum + bias);
        }
    }
}

// ---------------------------------------------------------------------------
// Sequential scan, 4-way split per (b,h): row-half x col-half -> 256 blocks,
// 128 threads each, 2 blocks/SM co-resident -> 2 warps/SMSP (TLP fix).
// Thread owns 2 rows x 4 cols (2 f32x2 per row). Col halves write partial
// outputs to separate buffers; ln_gate sums them.
// ---------------------------------------------------------------------------
#define TILE 16
#define NTILE (SS/TILE)
#define PART_STRIDE 260
#define SC_K(bufi)   ((bufi)*TILE*64)
#define SC_V(bufi)   (2*TILE*64 + (bufi)*TILE*64)
#define SC_Q(bufi)   (4*TILE*64 + (bufi)*TILE*64)
#define SC_AB        (6*TILE*64)
#define SC_W         (6*TILE*64 + SS*2)
#define SC_PART      (6*TILE*64 + SS*2 + TILE*64)
#define SCAN_SMEM_FL (SC_PART + TILE*PART_STRIDE)
#define SCAN_SMEM_SZ (SCAN_SMEM_FL*4)

__global__ __launch_bounds__(128, 2) void scan_kernel(const float* __restrict__ proj,
                                                      const float* __restrict__ ab,
                                                      float* __restrict__ attnA,
                                                      float* __restrict__ attnB)
{
    extern __shared__ float sh[];
    const int bid   = blockIdx.x;          // 0..255
    const int chain = bid >> 2;            // 0..63
    const int rhalf = (bid >> 1) & 1;
    const int chalf = bid & 1;
    const int b     = chain >> 4;
    const int h     = chain & 15;
    const int tid   = threadIdx.x;         // 0..127
    const int rp    = tid >> 3;            // 0..15 (row pair)
    const int cg    = tid & 7;             // col group (4 cols)
    const int i0    = rhalf*32 + rp*2;     // first state row (global 0..63)
    const int cbase = chalf*32 + cg*4;     // first col (global)

    float* attn = chalf ? attnB : attnA;

    const float* q = proj;
    const float* k = proj + HH;
    const float* v = proj + 2*HH;

    auto base  = [&](int t) { return ((size_t)(b*SS + t) * PW + (size_t)h*HDD); };
    auto abase = [&](int t) { return ((size_t)(b*SS + t) * HH + (size_t)h*HDD); };

    {
        #pragma unroll
        for (int it = 0; it < 2; ++it) {
            const int n  = tid + it*128;
            const int tt = n >> 4;
            const int e4 = (n & 15) << 2;
            cp_async16(&sh[SC_K(0) + tt*64 + e4], k + base(tt) + e4);
            cp_async16(&sh[SC_V(0) + tt*64 + e4], v + base(tt) + e4);
            cp_async16(&sh[SC_Q(0) + tt*64 + e4], q + base(tt) + e4);
        }
        cp_async_commit();
    }
    for (int t = tid; t < SS; t += 128) {
        const size_t o = (size_t)(b*SS + t) * 32;
        sh[SC_AB + t*2 + 0] = ab[o + h];
        sh[SC_AB + t*2 + 1] = ab[o + 16 + h];
    }
    cp_async_wait0();
    __syncthreads();

    ull s0[2], s1[2];
    #pragma unroll
    for (int j = 0; j < 2; ++j) { s0[j] = 0ull; s1[j] = 0ull; }

    int buf = 0;
    for (int tile = 0; tile < NTILE; ++tile) {
        const int t0 = tile * TILE;
        if (tile + 1 < NTILE) {
            const int nx = buf ^ 1;
            #pragma unroll
            for (int it = 0; it < 2; ++it) {
                const int n  = tid + it*128;
                const int tt = n >> 4;
                const int e4 = (n & 15) << 2;
                const size_t nb = base(t0 + TILE + tt) + e4;
                cp_async16(&sh[SC_K(nx) + tt*64 + e4], k + nb);
                cp_async16(&sh[SC_V(nx) + tt*64 + e4], v + nb);
                cp_async16(&sh[SC_Q(nx) + tt*64 + e4], q + nb);
            }
            cp_async_commit();
        }

        // ---- activation pass: l2norm(k,q), silu(v), w = beta*khat ----
        {
            const int tt2 = tid >> 3;
            const int e   = (tid & 7) * 8;
            const float be = sh[SC_AB + (t0 + tt2)*2 + 1];
            float* kr = &sh[SC_K(buf) + tt2*64];
            float* qr = &sh[SC_Q(buf) + tt2*64];
            float* vr = &sh[SC_V(buf) + tt2*64];

            float4 ka = *(float4*)&kr[e], kb = *(float4*)&kr[e+4];
            float4 qa = *(float4*)&qr[e], qb = *(float4*)&qr[e+4];
            float ssk = ka.x*ka.x + ka.y*ka.y + ka.z*ka.z + ka.w*ka.w
                      + kb.x*kb.x + kb.y*kb.y + kb.z*kb.z + kb.w*kb.w;
            float ssq = qa.x*qa.x + qa.y*qa.y + qa.z*qa.z + qa.w*qa.w
                      + qb.x*qb.x + qb.y*qb.y + qb.z*qb.z + qb.w*qb.w;
            #pragma unroll
            for (int off = 4; off; off >>= 1) {
                ssk += __shfl_xor_sync(0xffffffffu, ssk, off);
                ssq += __shfl_xor_sync(0xffffffffu, ssq, off);
            }
            const float invk = 1.f / fmaxf(sqrtf(ssk), 1e-12f);
            const float invq = 1.f / fmaxf(sqrtf(ssq), 1e-12f);
            ka.x*=invk; ka.y*=invk; ka.z*=invk; ka.w*=invk;
            kb.x*=invk; kb.y*=invk; kb.z*=invk; kb.w*=invk;
            qa.x*=invq; qa.y*=invq; qa.z*=invq; qa.w*=invq;
            qb.x*=invq; qb.y*=invq; qb.z*=invq; qb.w*=invq;
            *(float4*)&kr[e]   = ka;  *(float4*)&kr[e+4] = kb;
            *(float4*)&qr[e]   = qa;  *(float4*)&qr[e+4] = qb;
            *(float4*)&sh[SC_W + tt2*64 + e]   = make_float4(be*ka.x, be*ka.y, be*ka.z, be*ka.w);
            *(float4*)&sh[SC_W + tt2*64 + e+4] = make_float4(be*kb.x, be*kb.y, be*kb.z, be*kb.w);

            float4 va = *(float4*)&vr[e], vb = *(float4*)&vr[e+4];
            va.x = fsilu(va.x); va.y = fsilu(va.y); va.z = fsilu(va.z); va.w = fsilu(va.w);
            vb.x = fsilu(vb.x); vb.y = fsilu(vb.y); vb.z = fsilu(vb.z); vb.w = fsilu(vb.w);
            *(float4*)&vr[e]   = va;  *(float4*)&vr[e+4] = vb;
        }
        __syncthreads();

        const float* skb = &sh[SC_K(buf)];
        const float* svb = &sh[SC_V(buf)];
        const float* sqb = &sh[SC_Q(buf)];

        // register double-buffer for per-step operands (2 f32x2 w/q per thread)
        ull    w2[2][2], q2[2][2];
        float2 kif[2], vif[2];
        float  av[2];

        {
            const ulonglong2* wp = (const ulonglong2*)&sh[SC_W + cbase];
            const ulonglong2* qp = (const ulonglong2*)&sqb[cbase];
            ulonglong2 ww = wp[0], qq = qp[0];
            w2[0][0]=ww.x; w2[0][1]=ww.y;
            q2[0][0]=qq.x; q2[0][1]=qq.y;
            kif[0] = *(const float2*)&skb[i0];
            vif[0] = *(const float2*)&svb[i0];
            av[0]  = sh[SC_AB + t0*2];
        }

        #pragma unroll
        for (int tt = 0; tt < TILE; ++tt) {
            const int cur = tt & 1;
            const int nxt = cur ^ 1;
            if (tt + 1 < TILE) {
                const ulonglong2* wp = (const ulonglong2*)&sh[SC_W + (tt+1)*64 + cbase];
                const ulonglong2* qp = (const ulonglong2*)&sqb[(tt+1)*64 + cbase];
                ulonglong2 ww = wp[0], qq = qp[0];
                w2[nxt][0]=ww.x; w2[nxt][1]=ww.y;
                q2[nxt][0]=qq.x; q2[nxt][1]=qq.y;
                kif[nxt] = *(const float2*)&skb[(tt+1)*64 + i0];
                vif[nxt] = *(const float2*)&svb[(tt+1)*64 + i0];
                av[nxt]  = sh[SC_AB + (t0+tt+1)*2];
            }

            const ull a2  = pk2(av[cur], av[cur]);
            const ull nk0 = pk2(-kif[cur].x, -kif[cur].x);
            const ull nk1 = pk2(-kif[cur].y, -kif[cur].y);
            const ull v0  = pk2(vif[cur].x, vif[cur].x);
            const ull v1  = pk2(vif[cur].y, vif[cur].y);

            ull p0 = 0ull, p1 = 0ull;
            #pragma unroll
            for (int j = 0; j < 2; ++j) {
                const ull r0  = mul2(a2, s0[j]);
                const ull t0v = fma2(nk0, r0, v0);
                s0[j] = fma2(w2[cur][j], t0v, r0);
                const ull r1  = mul2(a2, s1[j]);
                const ull t1v = fma2(nk1, r1, v1);
                s1[j] = fma2(w2[cur][j], t1v, r1);
                p0 = fma2(s0[j], q2[cur][j], p0);
                p1 = fma2(s1[j], q2[cur][j], p1);
            }
            const float2 x0 = upk2(p0);
            const float2 x1 = upk2(p1);
            sh[SC_PART + tt*PART_STRIDE + (rp*2+0)*8 + cg] = x0.x + x0.y;
            sh[SC_PART + tt*PART_STRIDE + (rp*2+1)*8 + cg] = x1.x + x1.y;
        }
        __syncthreads();

        // tile reduction: thread -> (step tt = tid&15, 4 local rows)
        {
            const int tt   = tid & 15;
            const int rowg = tid >> 4;     // 0..7 -> local rows rowg*4..+3
            const float* p0 = &sh[SC_PART + tt*PART_STRIDE + rowg*32];
            float out[4];
            #pragma unroll
            for (int r = 0; r < 4; ++r) {
                float4 u0 = *(const float4*)(p0 + r*8);
                float4 u1 = *(const float4*)(p0 + r*8 + 4);
                out[r] = (u0.x+u0.y)+(u0.z+u0.w) + (u1.x+u1.y)+(u1.z+u1.w);
            }
            *(float4*)&attn[abase(t0 + tt) + rhalf*32 + rowg*4] =
                make_float4(out[0], out[1], out[2], out[3]);
        }

        if (tile + 1 < NTILE) cp_async_wait0();
        __syncthreads();
        buf ^= 1;
    }
}

// ---------------------------------------------------------------------------
// layernorm over H + gate; attn = A + B (col-half partials); z -> tf32
// ---------------------------------------------------------------------------
__global__ __launch_bounds__(256) void ln_gate_kernel(const float* __restrict__ attnA,
                                                      const float* __restrict__ attnB,
                                                      const float* __restrict__ proj,
                                                      const float* __restrict__ ln_g,
                                                      const float* __restrict__ ln_b,
                                                      float* __restrict__ z)
{
    const int m   = blockIdx.x;
    const int tid = threadIdx.x;
    const size_t rb = (size_t)m * HH + tid*4;

    float4 xa = *(const float4*)&attnA[rb];
    float4 xb = *(const float4*)&attnB[rb];
    float4 xv = make_float4(xa.x+xb.x, xa.y+xb.y, xa.z+xb.z, xa.w+xb.w);

    float s  = xv.x + xv.y + xv.z + xv.w;
    float ss = xv.x*xv.x + xv.y*xv.y + xv.z*xv.z + xv.w*xv.w;
    #pragma unroll
    for (int off = 16; off; off >>= 1) {
        s  += __shfl_xor_sync(0xffffffffu, s,  off);
        ss += __shfl_xor_sync(0xffffffffu, ss, off);
    }
    __shared__ float rs[8], rss[8];
    if ((tid & 31) == 0) { rs[tid>>5] = s; rss[tid>>5] = ss; }
    __syncthreads();
    float tot = 0.f, tots = 0.f;
    #pragma unroll
    for (int w = 0; w < 8; ++w) { tot += rs[w]; tots += rss[w]; }

    const float mean = tot * (1.f/HH);
    const float var  = tots * (1.f/HH) - mean*mean;
    const float inv  = rsqrtf(var + 1e-5f);

    float4 gv = *(const float4*)&proj[(size_t)m*PW + 3*HH + tid*4];
    float4 lg = *(const float4*)&ln_g[tid*4];
    float4 lb = *(const float4*)&ln_b[tid*4];

    float4 o;
    o.x = to_tf32(((xv.x-mean)*inv*lg.x + lb.x) * fsilu(gv.x));
    o.y = to_tf32(((xv.y-mean)*inv*lg.y + lb.y) * fsilu(gv.y));
    o.z = to_tf32(((xv.z-mean)*inv*lg.z + lb.z) * fsilu(gv.z));
    o.w = to_tf32(((xv.w-mean)*inv*lg.w + lb.w) * fsilu(gv.w));
    *(float4*)&z[rb] = o;
}

// ---------------------------------------------------------------------------
extern "C" void kernel_launch(void* const* d_in, const int* in_sizes, int n_in,
                              void* d_out, int out_size)
{
    const float* x    = (const float*)d_in[0];
    const float* Wq   = (const float*)d_in[1];
    const float* Wk   = (const float*)d_in[2];
    const float* Wv   = (const float*)d_in[3];
    const float* Wa   = (const float*)d_in[4];
    const float* ba   = (const float*)d_in[5];
    const float* Wb   = (const float*)d_in[6];
    const float* bb   = (const float*)d_in[7];
    const float* Wg   = (const float*)d_in[8];
    const float* Wo   = (const float*)d_in[9];
    const float* ln_g = (const float*)d_in[10];
    const float* ln_b = (const float*)d_in[11];
    float* out = (float*)d_out;

    float *projp, *abp, *attnp, *attn2p, *zp, *xrp, *wrp;
    cudaGetSymbolAddress((void**)&projp,  g_proj);
    cudaGetSymbolAddress((void**)&abp,    g_ab);
    cudaGetSymbolAddress((void**)&attnp,  g_attn);
    cudaGetSymbolAddress((void**)&attn2p, g_attn2);
    cudaGetSymbolAddress((void**)&zp,     g_z);
    cudaGetSymbolAddress((void**)&xrp,    g_xr);
    cudaGetSymbolAddress((void**)&wrp,    g_wr);

    float* wo_r = wrp + 4*(size_t)HH*HH;

    cudaFuncSetAttribute(gemm_tf32, cudaFuncAttributeMaxDynamicSharedMemorySize, GSMEM_SZ);
    cudaFuncSetAttribute(scan_kernel, cudaFuncAttributeMaxDynamicSharedMemorySize, SCAN_SMEM_SZ);

    const int round_blocks = (MM*HH + 5*HH*HH) / (4*256);

    // 0: fused tf32 rounding
    round_all<<<round_blocks, 256>>>(x, Wq, Wk, Wv, Wg, Wo, xrp, wrp);
    // 1: alpha/beta
    ab_kernel<<<MM/8, 256>>>(x, Wa, ba, Wb, bb, abp);
    // 2: fused QKVG projection
    dim3 grid_qkvg(PW/128, MM/128);
    gemm_tf32<<<grid_qkvg, 256, GSMEM_SZ>>>(xrp, wrp, projp, PW);
    // 3: scan (capture slot), 4-way split per chain
    scan_kernel<<<4*BB*NHH, 128, SCAN_SMEM_SZ>>>(projp, abp, attnp, attn2p);
    // 4: LN + gate (sums col-half partials)
    ln_gate_kernel<<<MM, 256>>>(attnp, attn2p, projp, ln_g, ln_b, zp);
    // 5: output projection
    dim3 grid_o(HH/128, MM/128);
    gemm_tf32<<<grid_o, 256, GSMEM_SZ>>>(zp, wo_r, out, HH);
}

// round 14
// speedup vs baseline: 1.2845x; 1.0275x over previous
#include <cuda_runtime.h>
#include <math.h>

#define BB   4
#define SS   2048
#define HH   1024
#define NHH  16
#define HDD  64
#define MM   (BB*SS)   /* 8192 tokens */
#define PW   4096      /* packed proj width: q|k|v|g */

// ---------------- scratch (device globals: allocation-free) ----------------
__device__ float g_proj[(size_t)MM*PW];
__device__ float g_ab[(size_t)MM*2*NHH];
__device__ float g_attn[(size_t)MM*HH];    // col-half 0 partial
__device__ float g_attn2[(size_t)MM*HH];   // col-half 1 partial
__device__ float g_z[(size_t)MM*HH];
__device__ float g_xr[(size_t)MM*HH];
__device__ float g_wr[(size_t)5*HH*HH];

// ---------------------------------------------------------------------------
// packed f32x2 helpers
// ---------------------------------------------------------------------------
typedef unsigned long long ull;
__device__ __forceinline__ ull pk2(float x, float y) {
    ull r; asm("mov.b64 %0, {%1,%2};" : "=l"(r) : "f"(x), "f"(y)); return r;
}
__device__ __forceinline__ ull mul2(ull a, ull b) {
    ull d; asm("mul.rn.f32x2 %0, %1, %2;" : "=l"(d) : "l"(a), "l"(b)); return d;
}
__device__ __forceinline__ ull add2(ull a, ull b) {
    ull d; asm("add.rn.f32x2 %0, %1, %2;" : "=l"(d) : "l"(a), "l"(b)); return d;
}
__device__ __forceinline__ ull fma2(ull a, ull b, ull c) {
    ull d; asm("fma.rn.f32x2 %0, %1, %2, %3;" : "=l"(d) : "l"(a), "l"(b), "l"(c)); return d;
}
__device__ __forceinline__ float2 upk2(ull a) {
    float2 f; asm("mov.b64 {%0,%1}, %2;" : "=f"(f.x), "=f"(f.y) : "l"(a)); return f;
}

__device__ __forceinline__ void cp_async16(void* dst_smem, const void* src_gmem) {
    unsigned dst = (unsigned)__cvta_generic_to_shared(dst_smem);
    asm volatile("cp.async.cg.shared.global [%0], [%1], 16;\n" :: "r"(dst), "l"(src_gmem));
}
__device__ __forceinline__ void cp_async_commit() {
    asm volatile("cp.async.commit_group;\n");
}
__device__ __forceinline__ void cp_async_wait0() {
    asm volatile("cp.async.wait_group 0;\n");
}

__device__ __forceinline__ float to_tf32(float x) {
    unsigned u; asm("cvt.rna.tf32.f32 %0, %1;" : "=r"(u) : "f"(x));
    return __uint_as_float(u);
}

__device__ __forceinline__ float fsigmoid(float x) {
    return 1.f / (1.f + __expf(-x));
}
__device__ __forceinline__ float fsilu(float x) {
    return x / (1.f + __expf(-x));
}

#define LDSM_X4(r0, r1, r2, r3, addr) \
    asm volatile("ldmatrix.sync.aligned.m8n8.x4.shared.b16 {%0,%1,%2,%3}, [%4];" \
        : "=r"(r0), "=r"(r1), "=r"(r2), "=r"(r3) : "r"(addr))

// ---------------------------------------------------------------------------
// tf32 tensor-core GEMM (unchanged from R11)
// ---------------------------------------------------------------------------
#define GS      3
#define CHK     32
#define NCHK    (HH/CHK)
#define LDA     36
#define TILE_FL (128*LDA)
#define STG_FL  (2*TILE_FL)
#define GSMEM_SZ (GS*STG_FL*4)

__device__ __forceinline__ void mma_tf32(float* c, const unsigned* a, const unsigned* b) {
    asm volatile(
        "mma.sync.aligned.m16n8k8.row.col.f32.tf32.tf32.f32 "
        "{%0,%1,%2,%3}, {%4,%5,%6,%7}, {%8,%9}, {%0,%1,%2,%3};"
        : "+f"(c[0]), "+f"(c[1]), "+f"(c[2]), "+f"(c[3])
        : "r"(a[0]), "r"(a[1]), "r"(a[2]), "r"(a[3]), "r"(b[0]), "r"(b[1]));
}

__device__ __forceinline__ void load_chunk_g(const float* __restrict__ A,
                                             const float* __restrict__ Bm,
                                             float* sm, int stage,
                                             int row0, int col0, int kbase, int tid)
{
    float* sa = sm + stage*STG_FL;
    float* sb = sa + TILE_FL;
    #pragma unroll
    for (int it = 0; it < 4; ++it) {
        const int n   = tid + it*256;
        const int row = n >> 3;
        const int fc  = (n & 7) << 2;
        cp_async16(sa + row*LDA + fc, A  + (size_t)(row0 + row)*HH + kbase + fc);
        cp_async16(sb + row*LDA + fc, Bm + (size_t)(col0 + row)*HH + kbase + fc);
    }
    cp_async_commit();
}

__global__ __launch_bounds__(256, 2) void gemm_tf32(const float* __restrict__ A,
                                                    const float* __restrict__ Bm,
                                                    float* __restrict__ C,
                                                    int ldc)
{
    extern __shared__ float sm[];
    const unsigned smu = (unsigned)__cvta_generic_to_shared(sm);
    const int tid  = threadIdx.x;
    const int wid  = tid >> 5;
    const int lane = tid & 31;
    const int wm   = wid & 1;
    const int wn   = wid >> 1;
    const int l4   = lane >> 2;
    const int lm   = lane & 3;
    const int row0 = blockIdx.y * 128;
    const int col0 = blockIdx.x * 128;

    const int tile = lane >> 3;
    const int trow = lane & 7;
    int a_byte[4], b_byte[2];
    #pragma unroll
    for (int mt = 0; mt < 4; ++mt)
        a_byte[mt] = ((wm*64 + mt*16 + ((tile & 1) << 3) + trow)*LDA
                      + ((tile >> 1) << 2)) * 4;
    #pragma unroll
    for (int p = 0; p < 2; ++p)
        b_byte[p] = ((wn*32 + (p*2 + (tile >> 1))*8 + trow)*LDA
                     + ((tile & 1) << 2)) * 4;

    float acc[4][4][4];
    #pragma unroll
    for (int mt = 0; mt < 4; ++mt)
        #pragma unroll
        for (int nt = 0; nt < 4; ++nt)
            #pragma unroll
            for (int r = 0; r < 4; ++r) acc[mt][nt][r] = 0.f;

    load_chunk_g(A, Bm, sm, 0, row0, col0, 0*CHK, tid);
    load_chunk_g(A, Bm, sm, 1, row0, col0, 1*CHK, tid);

    for (int c = 0; c < NCHK; ++c) {
        if (c + GS - 1 < NCHK)
            load_chunk_g(A, Bm, sm, (c + GS - 1) % GS, row0, col0, (c + GS - 1)*CHK, tid);

        if (c < NCHK - 2)       asm volatile("cp.async.wait_group 2;");
        else if (c == NCHK - 2) asm volatile("cp.async.wait_group 1;");
        else                    asm volatile("cp.async.wait_group 0;");
        __syncthreads();

        const unsigned sa_u = smu + ((unsigned)((c % GS)*STG_FL))*4u;
        const unsigned sb_u = sa_u + TILE_FL*4u;

        #pragma unroll
        for (int ks = 0; ks < 4; ++ks) {
            unsigned Af[4][4], Bf[2][4];
            #pragma unroll
            for (int mt = 0; mt < 4; ++mt)
                LDSM_X4(Af[mt][0], Af[mt][1], Af[mt][2], Af[mt][3],
                        sa_u + a_byte[mt] + ks*32);
            #pragma unroll
            for (int p = 0; p < 2; ++p)
                LDSM_X4(Bf[p][0], Bf[p][1], Bf[p][2], Bf[p][3],
                        sb_u + b_byte[p] + ks*32);
            #pragma unroll
            for (int mt = 0; mt < 4; ++mt)
                #pragma unroll
                for (int nt = 0; nt < 4; ++nt)
                    mma_tf32(acc[mt][nt], Af[mt], &Bf[nt >> 1][(nt & 1)*2]);
        }
        __syncthreads();
    }

    #pragma unroll
    for (int mt = 0; mt < 4; ++mt) {
        const int rg = row0 + wm*64 + mt*16 + l4;
        #pragma unroll
        for (int nt = 0; nt < 4; ++nt) {
            const int cg = col0 + wn*32 + nt*8 + lm*2;
            float* p = C + (size_t)rg*ldc + cg;
            *(float2*)p            = make_float2(acc[mt][nt][0], acc[mt][nt][1]);
            *(float2*)(p + 8*ldc)  = make_float2(acc[mt][nt][2], acc[mt][nt][3]);
        }
    }
}

// ---------------------------------------------------------------------------
// fused tf32 pre-rounding: x + 5 weights
// ---------------------------------------------------------------------------
__global__ __launch_bounds__(256) void round_all(const float* __restrict__ x,
                                                 const float* __restrict__ Wq,
                                                 const float* __restrict__ Wk,
                                                 const float* __restrict__ Wv,
                                                 const float* __restrict__ Wg,
                                                 const float* __restrict__ Wo,
                                                 float* __restrict__ xr,
                                                 float* __restrict__ wr)
{
    const size_t XC = (size_t)MM*HH/4;
    const size_t WC = (size_t)HH*HH/4;
    const size_t idx = (size_t)blockIdx.x * 256 + threadIdx.x;

    const float4* src;
    float4* dst;
    size_t off;
    if (idx < XC) {
        src = (const float4*)x; dst = (float4*)xr; off = idx;
    } else {
        const size_t r = idx - XC;
        const int w = (int)(r / WC);
        off = r % WC;
        const float* ws = (w == 0) ? Wq : (w == 1) ? Wk : (w == 2) ? Wv : (w == 3) ? Wg : Wo;
        src = (const float4*)ws;
        dst = (float4*)(wr + (size_t)w*HH*HH);
    }
    float4 v = src[off];
    v.x = to_tf32(v.x); v.y = to_tf32(v.y);
    v.z = to_tf32(v.z); v.w = to_tf32(v.w);
    dst[off] = v;
}

// ---------------------------------------------------------------------------
// alpha/beta
// ---------------------------------------------------------------------------
__global__ __launch_bounds__(256) void ab_kernel(const float* __restrict__ x,
                                                 const float* __restrict__ Wa,
                                                 const float* __restrict__ ba,
                                                 const float* __restrict__ Wb,
                                                 const float* __restrict__ bb,
                                                 float* __restrict__ ab)
{
    const int m0  = blockIdx.x * 8;
    const int tid = threadIdx.x;
    __shared__ float xs[8][HH];

    for (int n = tid; n < 8 * HH / 4; n += 256) {
        const int tok = n / (HH/4);
        const int e4  = (n % (HH/4)) * 4;
        *(float4*)&xs[tok][e4] = *(const float4*)&x[(size_t)(m0 + tok)*HH + e4];
    }
    __syncthreads();

    const int warp = tid >> 5, lane = tid & 31;
    for (int o = warp; o < 32; o += 8) {
        const float* w = (o < 16) ? (Wa + (size_t)o*HH) : (Wb + (size_t)(o-16)*HH);
        float wr[32];
        #pragma unroll
        for (int u = 0; u < 32; ++u) wr[u] = w[lane + u*32];
        const float bias = (o < 16) ? ba[o] : bb[o-16];
        for (int tok = 0; tok < 8; ++tok) {
            float sum = 0.f;
            #pragma unroll
            for (int u = 0; u < 32; ++u)
                sum = fmaf(wr[u], xs[tok][lane + u*32], sum);
            #pragma unroll
            for (int off = 16; off; off >>= 1)
                sum += __shfl_xor_sync(0xffffffffu, sum, off);
            if (lane == 0)
                ab[(size_t)(m0 + tok)*32 + o] = fsigmoid(sum + bias);
        }
    }
}

// ---------------------------------------------------------------------------
// Sequential scan, 4-way split per (b,h), LSU-minimized hot loop:
//   per step: LDS.128 w + LDS.128 q + LDS.128 kva{k0,v0,k1,v1} + STS.64 part.
// alpha preloaded to registers per tile; activation pass builds W and KVA
// (SC_K/SC_V have no consumers after it).
// ---------------------------------------------------------------------------
#define TILE 16
#define NTILE (SS/TILE)
// smem layout (floats)
#define SC_K(bufi)   ((bufi)*TILE*64)                 /* [0,2048)      */
#define SC_V(bufi)   (2*TILE*64 + (bufi)*TILE*64)     /* [2048,4096)   */
#define SC_Q(bufi)   (4*TILE*64 + (bufi)*TILE*64)     /* [4096,6144)   */
#define SC_SA        (6*TILE*64)                      /* alpha  [6144,8192) */
#define SC_SB        (6*TILE*64 + SS)                 /* beta   [8192,10240) */
#define SC_W         (6*TILE*64 + 2*SS)               /* [10240,11264) */
#define SC_KVA       (6*TILE*64 + 2*SS + TILE*64)     /* float4[TILE*16] [11264,12288) */
#define SC_PART      (6*TILE*64 + 2*SS + 2*TILE*64)   /* float2[TILE*130] */
#define SCAN_SMEM_FL (SC_PART + TILE*130*2)
#define SCAN_SMEM_SZ (SCAN_SMEM_FL*4)                 /* 65792 B */

__global__ __launch_bounds__(128, 2) void scan_kernel(const float* __restrict__ proj,
                                                      const float* __restrict__ ab,
                                                      float* __restrict__ attnA,
                                                      float* __restrict__ attnB)
{
    extern __shared__ float sh[];
    const int bid   = blockIdx.x;          // 0..255
    const int chain = bid >> 2;            // 0..63
    const int rhalf = (bid >> 1) & 1;
    const int chalf = bid & 1;
    const int b     = chain >> 4;
    const int h     = chain & 15;
    const int tid   = threadIdx.x;         // 0..127
    const int rp    = tid >> 3;            // 0..15 (row pair, local)
    const int cg    = tid & 7;             // col group (4 cols)
    const int cbase = chalf*32 + cg*4;     // first col (0..63)

    float* attn = chalf ? attnB : attnA;

    const float* q = proj;
    const float* k = proj + HH;
    const float* v = proj + 2*HH;

    auto base  = [&](int t) { return ((size_t)(b*SS + t) * PW + (size_t)h*HDD); };
    auto abase = [&](int t) { return ((size_t)(b*SS + t) * HH + (size_t)h*HDD); };

    {
        #pragma unroll
        for (int it = 0; it < 2; ++it) {
            const int n  = tid + it*128;
            const int tt = n >> 4;
            const int e4 = (n & 15) << 2;
            cp_async16(&sh[SC_K(0) + tt*64 + e4], k + base(tt) + e4);
            cp_async16(&sh[SC_V(0) + tt*64 + e4], v + base(tt) + e4);
            cp_async16(&sh[SC_Q(0) + tt*64 + e4], q + base(tt) + e4);
        }
        cp_async_commit();
    }
    for (int t = tid; t < SS; t += 128) {
        const size_t o = (size_t)(b*SS + t) * 32;
        sh[SC_SA + t] = ab[o + h];
        sh[SC_SB + t] = ab[o + 16 + h];
    }
    cp_async_wait0();
    __syncthreads();

    ull s0[2], s1[2];
    #pragma unroll
    for (int j = 0; j < 2; ++j) { s0[j] = 0ull; s1[j] = 0ull; }

    int buf = 0;
    for (int tile = 0; tile < NTILE; ++tile) {
        const int t0 = tile * TILE;
        if (tile + 1 < NTILE) {
            const int nx = buf ^ 1;
            #pragma unroll
            for (int it = 0; it < 2; ++it) {
                const int n  = tid + it*128;
                const int tt = n >> 4;
                const int e4 = (n & 15) << 2;
                const size_t nb = base(t0 + TILE + tt) + e4;
                cp_async16(&sh[SC_K(nx) + tt*64 + e4], k + nb);
                cp_async16(&sh[SC_V(nx) + tt*64 + e4], v + nb);
                cp_async16(&sh[SC_Q(nx) + tt*64 + e4], q + nb);
            }
            cp_async_commit();
        }

        // preload tile's alpha values into registers (SA is static)
        float al[TILE];
        #pragma unroll
        for (int u = 0; u < TILE/4; ++u)
            *(float4*)&al[u*4] = *(const float4*)&sh[SC_SA + t0 + u*4];

        // ---- activation pass: l2norm(k,q), silu(v), build W and KVA ----
        {
            const int tt2 = tid >> 3;        // step 0..15
            const int e   = (tid & 7) * 8;   // 8 cols per thread
            const float be = sh[SC_SB + t0 + tt2];
            const float* kr = &sh[SC_K(buf) + tt2*64];
            float* qr = &sh[SC_Q(buf) + tt2*64];
            const float* vr = &sh[SC_V(buf) + tt2*64];

            float4 ka = *(const float4*)&kr[e], kb = *(const float4*)&kr[e+4];
            float4 qa = *(float4*)&qr[e],       qb = *(float4*)&qr[e+4];
            float ssk = ka.x*ka.x + ka.y*ka.y + ka.z*ka.z + ka.w*ka.w
                      + kb.x*kb.x + kb.y*kb.y + kb.z*kb.z + kb.w*kb.w;
            float ssq = qa.x*qa.x + qa.y*qa.y + qa.z*qa.z + qa.w*qa.w
                      + qb.x*qb.x + qb.y*qb.y + qb.z*qb.z + qb.w*qb.w;
            #pragma unroll
            for (int off = 4; off; off >>= 1) {
                ssk += __shfl_xor_sync(0xffffffffu, ssk, off);
                ssq += __shfl_xor_sync(0xffffffffu, ssq, off);
            }
            const float invk = 1.f / fmaxf(sqrtf(ssk), 1e-12f);
            const float invq = 1.f / fmaxf(sqrtf(ssq), 1e-12f);
            ka.x*=invk; ka.y*=invk; ka.z*=invk; ka.w*=invk;
            kb.x*=invk; kb.y*=invk; kb.z*=invk; kb.w*=invk;
            qa.x*=invq; qa.y*=invq; qa.z*=invq; qa.w*=invq;
            qb.x*=invq; qb.y*=invq; qb.z*=invq; qb.w*=invq;
            *(float4*)&qr[e]   = qa;  *(float4*)&qr[e+4] = qb;
            *(float4*)&sh[SC_W + tt2*64 + e]   = make_float4(be*ka.x, be*ka.y, be*ka.z, be*ka.w);
            *(float4*)&sh[SC_W + tt2*64 + e+4] = make_float4(be*kb.x, be*kb.y, be*kb.z, be*kb.w);

            // KVA only for rows in this block's row window
            if ((e >> 5) == rhalf) {
                float4 va = *(const float4*)&vr[e], vb = *(const float4*)&vr[e+4];
                va.x = fsilu(va.x); va.y = fsilu(va.y); va.z = fsilu(va.z); va.w = fsilu(va.w);
                vb.x = fsilu(vb.x); vb.y = fsilu(vb.y); vb.z = fsilu(vb.z); vb.w = fsilu(vb.w);
                const int rpb = (e - rhalf*32) >> 1;   // 0,4,8,12
                float4* kvap = (float4*)&sh[SC_KVA + (tt2*16 + rpb)*4];
                kvap[0] = make_float4(ka.x, va.x, ka.y, va.y);
                kvap[1] = make_float4(ka.z, va.z, ka.w, va.w);
                kvap[2] = make_float4(kb.x, vb.x, kb.y, vb.y);
                kvap[3] = make_float4(kb.z, vb.z, kb.w, vb.w);
            }
        }
        __syncthreads();

        const float* sqb = &sh[SC_Q(buf)];

        // register double-buffer for per-step operands
        ull    w2[2][2], q2[2][2];
        float4 kva[2];

        {
            const ulonglong2* wp = (const ulonglong2*)&sh[SC_W + cbase];
            const ulonglong2* qp = (const ulonglong2*)&sqb[cbase];
            ulonglong2 ww = wp[0], qq = qp[0];
            w2[0][0]=ww.x; w2[0][1]=ww.y;
            q2[0][0]=qq.x; q2[0][1]=qq.y;
            kva[0] = *(const float4*)&sh[SC_KVA + rp*4];
        }

        #pragma unroll
        for (int tt = 0; tt < TILE; ++tt) {
            const int cur = tt & 1;
            const int nxt = cur ^ 1;
            if (tt + 1 < TILE) {
                const ulonglong2* wp = (const ulonglong2*)&sh[SC_W + (tt+1)*64 + cbase];
                const ulonglong2* qp = (const ulonglong2*)&sqb[(tt+1)*64 + cbase];
                ulonglong2 ww = wp[0], qq = qp[0];
                w2[nxt][0]=ww.x; w2[nxt][1]=ww.y;
                q2[nxt][0]=qq.x; q2[nxt][1]=qq.y;
                kva[nxt] = *(const float4*)&sh[SC_KVA + ((tt+1)*16 + rp)*4];
            }

            const ull a2  = pk2(al[tt], al[tt]);
            const ull nk0 = pk2(-kva[cur].x, -kva[cur].x);
            const ull v0  = pk2(kva[cur].y, kva[cur].y);
            const ull nk1 = pk2(-kva[cur].z, -kva[cur].z);
            const ull v1  = pk2(kva[cur].w, kva[cur].w);

            ull p0 = 0ull, p1 = 0ull;
            #pragma unroll
            for (int j = 0; j < 2; ++j) {
                const ull r0  = mul2(a2, s0[j]);
                const ull t0v = fma2(nk0, r0, v0);
                s0[j] = fma2(w2[cur][j], t0v, r0);
                const ull r1  = mul2(a2, s1[j]);
                const ull t1v = fma2(nk1, r1, v1);
                s1[j] = fma2(w2[cur][j], t1v, r1);
                p0 = fma2(s0[j], q2[cur][j], p0);
                p1 = fma2(s1[j], q2[cur][j], p1);
            }
            const float2 x0 = upk2(p0);
            const float2 x1 = upk2(p1);
            *(float2*)&sh[SC_PART + (tt*130 + rp*8 + cg)*2] =
                make_float2(x0.x + x0.y, x1.x + x1.y);
        }
        __syncthreads();

        // tile reduction: thread -> (step tt = tid&15, 4 local rows)
        {
            const int tt   = tid & 15;
            const int rowg = tid >> 4;     // 0..7 -> local rows rowg*4..+3
            const float* p0 = &sh[SC_PART + (tt*130 + rowg*16)*2];  // 32 floats
            float o0 = 0.f, o1 = 0.f, o2 = 0.f, o3 = 0.f;
            #pragma unroll
            for (int u = 0; u < 4; ++u) {
                float4 a4 = *(const float4*)(p0 + u*4);       // rp=2*rowg (rows 4g,4g+1)
                float4 b4 = *(const float4*)(p0 + 16 + u*4);  // rp=2*rowg+1 (rows 4g+2,4g+3)
                o0 += a4.x + a4.z;
                o1 += a4.y + a4.w;
                o2 += b4.x + b4.z;
                o3 += b4.y + b4.w;
            }
            *(float4*)&attn[abase(t0 + tt) + rhalf*32 + rowg*4] =
                make_float4(o0, o1, o2, o3);
        }

        if (tile + 1 < NTILE) cp_async_wait0();
        __syncthreads();
        buf ^= 1;
    }
}

// ---------------------------------------------------------------------------
// layernorm over H + gate; attn = A + B (col-half partials); z -> tf32
// ---------------------------------------------------------------------------
__global__ __launch_bounds__(256) void ln_gate_kernel(const float* __restrict__ attnA,
                                                      const float* __restrict__ attnB,
                                                      const float* __restrict__ proj,
                                                      const float* __restrict__ ln_g,
                                                      const float* __restrict__ ln_b,
                                                      float* __restrict__ z)
{
    const int m   = blockIdx.x;
    const int tid = threadIdx.x;
    const size_t rb = (size_t)m * HH + tid*4;

    float4 xa = *(const float4*)&attnA[rb];
    float4 xb = *(const float4*)&attnB[rb];
    float4 xv = make_float4(xa.x+xb.x, xa.y+xb.y, xa.z+xb.z, xa.w+xb.w);

    float s  = xv.x + xv.y + xv.z + xv.w;
    float ss = xv.x*xv.x + xv.y*xv.y + xv.z*xv.z + xv.w*xv.w;
    #pragma unroll
    for (int off = 16; off; off >>= 1) {
        s  += __shfl_xor_sync(0xffffffffu, s,  off);
        ss += __shfl_xor_sync(0xffffffffu, ss, off);
    }
    __shared__ float rs[8], rss[8];
    if ((tid & 31) == 0) { rs[tid>>5] = s; rss[tid>>5] = ss; }
    __syncthreads();
    float tot = 0.f, tots = 0.f;
    #pragma unroll
    for (int w = 0; w < 8; ++w) { tot += rs[w]; tots += rss[w]; }

    const float mean = tot * (1.f/HH);
    const float var  = tots * (1.f/HH) - mean*mean;
    const float inv  = rsqrtf(var + 1e-5f);

    float4 gv = *(const float4*)&proj[(size_t)m*PW + 3*HH + tid*4];
    float4 lg = *(const float4*)&ln_g[tid*4];
    float4 lb = *(const float4*)&ln_b[tid*4];

    float4 o;
    o.x = to_tf32(((xv.x-mean)*inv*lg.x + lb.x) * fsilu(gv.x));
    o.y = to_tf32(((xv.y-mean)*inv*lg.y + lb.y) * fsilu(gv.y));
    o.z = to_tf32(((xv.z-mean)*inv*lg.z + lb.z) * fsilu(gv.z));
    o.w = to_tf32(((xv.w-mean)*inv*lg.w + lb.w) * fsilu(gv.w));
    *(float4*)&z[rb] = o;
}

// ---------------------------------------------------------------------------
extern "C" void kernel_launch(void* const* d_in, const int* in_sizes, int n_in,
                              void* d_out, int out_size)
{
    const float* x    = (const float*)d_in[0];
    const float* Wq   = (const float*)d_in[1];
    const float* Wk   = (const float*)d_in[2];
    const float* Wv   = (const float*)d_in[3];
    const float* Wa   = (const float*)d_in[4];
    const float* ba   = (const float*)d_in[5];
    const float* Wb   = (const float*)d_in[6];
    const float* bb   = (const float*)d_in[7];
    const float* Wg   = (const float*)d_in[8];
    const float* Wo   = (const float*)d_in[9];
    const float* ln_g = (const float*)d_in[10];
    const float* ln_b = (const float*)d_in[11];
    float* out = (float*)d_out;

    float *projp, *abp, *attnp, *attn2p, *zp, *xrp, *wrp;
    cudaGetSymbolAddress((void**)&projp,  g_proj);
    cudaGetSymbolAddress((void**)&abp,    g_ab);
    cudaGetSymbolAddress((void**)&attnp,  g_attn);
    cudaGetSymbolAddress((void**)&attn2p, g_attn2);
    cudaGetSymbolAddress((void**)&zp,     g_z);
    cudaGetSymbolAddress((void**)&xrp,    g_xr);
    cudaGetSymbolAddress((void**)&wrp,    g_wr);

    float* wo_r = wrp + 4*(size_t)HH*HH;

    cudaFuncSetAttribute(gemm_tf32, cudaFuncAttributeMaxDynamicSharedMemorySize, GSMEM_SZ);
    cudaFuncSetAttribute(scan_kernel, cudaFuncAttributeMaxDynamicSharedMemorySize, SCAN_SMEM_SZ);

    const int round_blocks = (MM*HH + 5*HH*HH) / (4*256);

    // 0: fused tf32 rounding
    round_all<<<round_blocks, 256>>>(x, Wq, Wk, Wv, Wg, Wo, xrp, wrp);
    // 1: alpha/beta
    ab_kernel<<<MM/8, 256>>>(x, Wa, ba, Wb, bb, abp);
    // 2: fused QKVG projection
    dim3 grid_qkvg(PW/128, MM/128);
    gemm_tf32<<<grid_qkvg, 256, GSMEM_SZ>>>(xrp, wrp, projp, PW);
    // 3: scan (capture slot), 4-way split per chain
    scan_kernel<<<4*BB*NHH, 128, SCAN_SMEM_SZ>>>(projp, abp, attnp, attn2p);
    // 4: LN + gate (sums col-half partials)
    ln_gate_kernel<<<MM, 256>>>(attnp, attn2p, projp, ln_g, ln_b, zp);
    // 5: output projection
    dim3 grid_o(HH/128, MM/128);
    gemm_tf32<<<grid_o, 256, GSMEM_SZ>>>(zp, wo_r, out, HH);
}